// round 11
// baseline (speedup 1.0000x reference)
#include <cuda_runtime.h>
#include <cuda_fp16.h>
#include <cstdint>
#include <cstring>

#define B_   32
#define RES_ 56
#define C_   128
#define H_   4
#define HD_  32
#define WS_  7
#define NW_  8
#define NQ_  64
#define WA_  49
#define TOPK_ 64
#define KV_  128
#define P_   3136
#define M0_  (B_*P_)
#define M1_  (B_*NQ_)

__device__ __half g_qkv0[(size_t)M0_ * 384];
__device__ __half g_qkv1[(size_t)M1_ * 384];
__device__ __half g_rpb[(size_t)NQ_ * H_ * WA_ * KV_];
__device__ __half g_attn_out[(size_t)M0_ * C_];

#define MMA_F16(C0,C1,C2,C3,A0,A1,A2,A3,B0,B1) \
    asm volatile("mma.sync.aligned.m16n8k16.row.col.f32.f16.f16.f32 " \
        "{%0,%1,%2,%3},{%4,%5,%6,%7},{%8,%9},{%0,%1,%2,%3};" \
        : "+f"(C0), "+f"(C1), "+f"(C2), "+f"(C3) \
        : "r"(A0), "r"(A1), "r"(A2), "r"(A3), "r"(B0), "r"(B1))

#define LDSM_X4(R0,R1,R2,R3,ADDR) \
    asm volatile("ldmatrix.sync.aligned.m8n8.x4.shared.b16 {%0,%1,%2,%3}, [%4];" \
        : "=r"(R0), "=r"(R1), "=r"(R2), "=r"(R3) : "r"(ADDR))

__device__ __forceinline__ uint32_t sh_addr(const void* p) {
    return (uint32_t)__cvta_generic_to_shared(p);
}
__device__ __forceinline__ uint4 f4_to_h8(float4 a, float4 b) {
    __half2 h0 = __floats2half2_rn(a.x, a.y);
    __half2 h1 = __floats2half2_rn(a.z, a.w);
    __half2 h2 = __floats2half2_rn(b.x, b.y);
    __half2 h3 = __floats2half2_rn(b.z, b.w);
    uint4 u = {*(uint32_t*)&h0, *(uint32_t*)&h1, *(uint32_t*)&h2, *(uint32_t*)&h3};
    return u;
}
__device__ __forceinline__ uint32_t h2bits(float a, float b) {
    __half2 h = __floats2half2_rn(a, b);
    return *(uint32_t*)&h;
}

// ============================================================
// FP16-mma GEMM: C[M,N] = A[M,K]*B[N,K]^T + bias[N]
// ============================================================
template <typename TA, typename TO>
__global__ __launch_bounds__(256) void gemm_f16(
    const TA* __restrict__ A, const float* __restrict__ Bm,
    const float* __restrict__ bias, TO* __restrict__ C,
    int M, int N, int K)
{
    __shared__ __half As[128 * 40];
    __shared__ __half Bs[128 * 40];

    const int tid = threadIdx.x;
    const int m0 = blockIdx.x * 128;
    const int n0 = blockIdx.y * 128;
    const int warp = tid >> 5, lane = tid & 31;
    const int wm = (warp >> 2) * 64;
    const int wn = (warp & 3) * 32;
    const int r = lane >> 2;
    const int cI = lane & 3;

    const int a_row  = lane & 15;
    const int a_koff = (lane >> 4) * 8;
    const int b_row  = (lane & 7) + (lane >> 4) * 8;
    const int b_koff = ((lane >> 3) & 1) * 8;

    float c[4][4][4];
#pragma unroll
    for (int mt = 0; mt < 4; mt++)
#pragma unroll
        for (int nt = 0; nt < 4; nt++)
#pragma unroll
            for (int f = 0; f < 4; f++) c[mt][nt][f] = 0.f;

    const int lr = tid >> 1;
    const int ls = (tid & 1) * 16;
    const TA*    Arow = A  + (size_t)(m0 + lr) * K + ls;
    const float* Brow = Bm + (size_t)(n0 + lr) * K + ls;

    float4 ra[4];
    uint4  rah[2];
    float4 rb[4];
    if constexpr (sizeof(TA) == 4) {
#pragma unroll
        for (int q = 0; q < 4; q++) ra[q] = *(const float4*)((const float*)Arow + q * 4);
    } else {
        rah[0] = *(const uint4*)((const __half*)Arow);
        rah[1] = *(const uint4*)((const __half*)Arow + 8);
    }
#pragma unroll
    for (int q = 0; q < 4; q++) rb[q] = *(const float4*)(Brow + q * 4);

    for (int k0 = 0; k0 < K; k0 += 32) {
        if constexpr (sizeof(TA) == 4) {
            *(uint4*)&As[lr * 40 + ls]     = f4_to_h8(ra[0], ra[1]);
            *(uint4*)&As[lr * 40 + ls + 8] = f4_to_h8(ra[2], ra[3]);
        } else {
            *(uint4*)&As[lr * 40 + ls]     = rah[0];
            *(uint4*)&As[lr * 40 + ls + 8] = rah[1];
        }
        *(uint4*)&Bs[lr * 40 + ls]     = f4_to_h8(rb[0], rb[1]);
        *(uint4*)&Bs[lr * 40 + ls + 8] = f4_to_h8(rb[2], rb[3]);
        __syncthreads();

        if (k0 + 32 < K) {
            if constexpr (sizeof(TA) == 4) {
#pragma unroll
                for (int q = 0; q < 4; q++)
                    ra[q] = *(const float4*)((const float*)Arow + k0 + 32 + q * 4);
            } else {
                rah[0] = *(const uint4*)((const __half*)Arow + k0 + 32);
                rah[1] = *(const uint4*)((const __half*)Arow + k0 + 40);
            }
#pragma unroll
            for (int q = 0; q < 4; q++)
                rb[q] = *(const float4*)(Brow + k0 + 32 + q * 4);
        }

#pragma unroll
        for (int k16 = 0; k16 < 32; k16 += 16) {
            uint32_t a[4][4], b[4][2];
#pragma unroll
            for (int mt = 0; mt < 4; mt++) {
                uint32_t ad = sh_addr(&As[(wm + mt * 16 + a_row) * 40 + k16 + a_koff]);
                LDSM_X4(a[mt][0], a[mt][1], a[mt][2], a[mt][3], ad);
            }
#pragma unroll
            for (int np = 0; np < 2; np++) {
                uint32_t ad = sh_addr(&Bs[(wn + np * 16 + b_row) * 40 + k16 + b_koff]);
                LDSM_X4(b[2 * np][0], b[2 * np][1], b[2 * np + 1][0], b[2 * np + 1][1], ad);
            }
#pragma unroll
            for (int mt = 0; mt < 4; mt++)
#pragma unroll
                for (int nt = 0; nt < 4; nt++)
                    MMA_F16(c[mt][nt][0], c[mt][nt][1], c[mt][nt][2], c[mt][nt][3],
                            a[mt][0], a[mt][1], a[mt][2], a[mt][3],
                            b[nt][0], b[nt][1]);
        }
        __syncthreads();
    }

#pragma unroll
    for (int mt = 0; mt < 4; mt++) {
        const int row = m0 + wm + mt * 16 + r;
#pragma unroll
        for (int nt = 0; nt < 4; nt++) {
            const int col = n0 + wn + nt * 8 + cI * 2;
            float2 bb = *(const float2*)&bias[col];
            if constexpr (sizeof(TO) == 4) {
                float2 o0 = {c[mt][nt][0] + bb.x, c[mt][nt][1] + bb.y};
                float2 o1 = {c[mt][nt][2] + bb.x, c[mt][nt][3] + bb.y};
                *(float2*)&((float*)C)[(size_t)row * N + col]       = o0;
                *(float2*)&((float*)C)[(size_t)(row + 8) * N + col] = o1;
            } else {
                uint32_t o0 = h2bits(c[mt][nt][0] + bb.x, c[mt][nt][1] + bb.y);
                uint32_t o1 = h2bits(c[mt][nt][2] + bb.x, c[mt][nt][3] + bb.y);
                *(uint32_t*)&((__half*)C)[(size_t)row * N + col]       = o0;
                *(uint32_t*)&((__half*)C)[(size_t)(row + 8) * N + col] = o1;
            }
        }
    }
}

// ============================================================
// RPB MLP precompute -> fp16 table
// ============================================================
__global__ void rpb_kernel(
    const float* __restrict__ coords0, const float* __restrict__ coords1,
    const float* __restrict__ w1a, const float* __restrict__ b1a,
    const float* __restrict__ w2a, const float* __restrict__ b2a,
    const float* __restrict__ w1b, const float* __restrict__ b1b,
    const float* __restrict__ w2b, const float* __restrict__ b2b,
    __half* __restrict__ rpb)
{
    int t = blockIdx.x * blockDim.x + threadIdx.x;
    const int TOT = NQ_ * WA_ * KV_;
    if (t >= TOT) return;
    int j = t & 127;
    int i = (t >> 7) % WA_;
    int w = t / (KV_ * WA_);

    const float *co, *w1, *b1, *w2, *b2;
    int jj;
    if (j < TOPK_) { co = coords0; jj = j;          w1 = w1a; b1 = b1a; w2 = w2a; b2 = b2a; }
    else           { co = coords1; jj = j - TOPK_;  w1 = w1b; b1 = b1b; w2 = w2b; b2 = b2b; }

    size_t cbase = ((size_t)(w * WA_ + i) * TOPK_ + jj) * 2;
    float cy = co[cbase + 0];
    float cx = co[cbase + 1];

    float o0 = b2[0], o1 = b2[1], o2 = b2[2], o3 = b2[3];
#pragma unroll
    for (int tt = 0; tt < HD_; tt++) {
        float hsum = fmaxf(fmaf(w1[tt * 2], cy, fmaf(w1[tt * 2 + 1], cx, b1[tt])), 0.f);
        o0 = fmaf(w2[0 * HD_ + tt], hsum, o0);
        o1 = fmaf(w2[1 * HD_ + tt], hsum, o1);
        o2 = fmaf(w2[2 * HD_ + tt], hsum, o2);
        o3 = fmaf(w2[3 * HD_ + tt], hsum, o3);
    }
    size_t base = ((size_t)(w * H_) * WA_ + i) * KV_ + j;
    const size_t hstride = (size_t)WA_ * KV_;
    rpb[base + 0 * hstride] = __float2half(o0);
    rpb[base + 1 * hstride] = __float2half(o1);
    rpb[base + 2 * hstride] = __float2half(o2);
    rpb[base + 3 * hstride] = __float2half(o3);
}

// ============================================================
// FP16 tensor-core attention (44288 B smem, 5 CTAs/SM)
// rpb fused into QK epilogue (parallel loads, fp16 table)
// ============================================================
#define SMEM_ATTN 44288

__global__ __launch_bounds__(256, 5) void attn_mma(
    const int* __restrict__ idx0, const int* __restrict__ idx1,
    const __half* __restrict__ rpb,
    const __half* __restrict__ qkv0, const __half* __restrict__ qkv1,
    __half* __restrict__ attn_out)
{
    extern __shared__ char smem_raw[];
    __half* k_s  = (__half*)(smem_raw);
    __half* vT_s = (__half*)(smem_raw);                 // alias after QK
    float*  p_s  = (float*) (smem_raw + 10240);
    __half* q_s  = (__half*)(smem_raw + 10240);         // alias (dead after QK)
    float*  inv_s= (float*) (smem_raw + 44032);
    char*   p_base = smem_raw + 10240;

    const int w = blockIdx.x, b = blockIdx.y, h = blockIdx.z;
    const int tid = threadIdx.x;
    const int warp = tid >> 5, lane = tid & 31;
    const int r = lane >> 2, cI = lane & 3;

    const int a_row  = lane & 15;
    const int a_koff = (lane >> 4) * 8;
    const int b_row  = (lane & 7) + (lane >> 4) * 8;
    const int b_koff = ((lane >> 3) & 1) * 8;

    // ---- gather K: 2 threads per key row ----
    const int j = tid >> 1;
    const int half16 = (tid & 1) * 16;
    const __half* basep;
    if (j < TOPK_) basep = qkv0 + ((size_t)b * P_ + idx0[w * TOPK_ + j]) * 384;
    else           basep = qkv1 + ((size_t)b * NQ_ + idx1[w * TOPK_ + (j - TOPK_)]) * 384;

    {
        const uint4* kp = (const uint4*)(basep + C_ + h * HD_ + half16);
        uint4 k0 = kp[0], k1 = kp[1];
        *(uint4*)&k_s[j * 40 + half16]     = k0;
        *(uint4*)&k_s[j * 40 + half16 + 8] = k1;
    }

    // ---- load Q (49 rows, pad to 64): 8 halves per thread ----
    const int wy = w >> 3, wx = w & 7;
    {
        int i = tid >> 2, d = (tid & 3) * 8;
        uint4 val = {0u, 0u, 0u, 0u};
        if (i < WA_) {
            int pos = (wy * WS_ + i / WS_) * RES_ + wx * WS_ + i % WS_;
            val = *(const uint4*)(qkv0 + ((size_t)b * P_ + pos) * 384 + h * HD_ + d);
        }
        *(uint4*)&q_s[i * 40 + d] = val;
    }
    __syncthreads();

    // ---- QK: M=64 N=128 K=32 ----
    float cq[2][4][4];
    {
        const int wm = (warp & 1) * 32, wn = (warp >> 1) * 32;
#pragma unroll
        for (int mt = 0; mt < 2; mt++)
#pragma unroll
            for (int nt = 0; nt < 4; nt++)
#pragma unroll
                for (int f = 0; f < 4; f++) cq[mt][nt][f] = 0.f;

#pragma unroll
        for (int k16 = 0; k16 < 32; k16 += 16) {
            uint32_t a[2][4], bb[4][2];
#pragma unroll
            for (int mt = 0; mt < 2; mt++) {
                uint32_t ad = sh_addr(&q_s[(wm + mt * 16 + a_row) * 40 + k16 + a_koff]);
                LDSM_X4(a[mt][0], a[mt][1], a[mt][2], a[mt][3], ad);
            }
#pragma unroll
            for (int np = 0; np < 2; np++) {
                uint32_t ad = sh_addr(&k_s[(wn + np * 16 + b_row) * 40 + k16 + b_koff]);
                LDSM_X4(bb[2 * np][0], bb[2 * np][1], bb[2 * np + 1][0], bb[2 * np + 1][1], ad);
            }
#pragma unroll
            for (int mt = 0; mt < 2; mt++)
#pragma unroll
                for (int nt = 0; nt < 4; nt++)
                    MMA_F16(cq[mt][nt][0], cq[mt][nt][1], cq[mt][nt][2], cq[mt][nt][3],
                            a[mt][0], a[mt][1], a[mt][2], a[mt][3],
                            bb[nt][0], bb[nt][1]);
        }
    }

    // ---- issue V gather + rpb loads (no smem dependence, all parallel) ----
    uint4 vu0, vu1;
    {
        const uint4* vp = (const uint4*)(basep + 2 * C_ + h * HD_ + half16);
        vu0 = vp[0]; vu1 = vp[1];
    }
    const float scale = 0.17677669529663687f;
    const __half* rpb_wh = rpb + (size_t)(w * H_ + h) * WA_ * KV_;
    float2 rpbv[2][4][2];   // [mt][nt][rowhalf] half2->float2
    {
        const int wm = (warp & 1) * 32, wn = (warp >> 1) * 32;
#pragma unroll
        for (int mt = 0; mt < 2; mt++) {
            const int row0 = wm + mt * 16 + r;
            const int row1 = row0 + 8;
#pragma unroll
            for (int nt = 0; nt < 4; nt++) {
                const int col = wn + nt * 8 + cI * 2;
                __half2 h0 = (row0 < WA_) ? *(const __half2*)&rpb_wh[row0 * KV_ + col]
                                          : __half2{__half(0.f), __half(0.f)};
                __half2 h1 = (row1 < WA_) ? *(const __half2*)&rpb_wh[row1 * KV_ + col]
                                          : __half2{__half(0.f), __half(0.f)};
                rpbv[mt][nt][0] = __half22float2(h0);
                rpbv[mt][nt][1] = __half22float2(h1);
            }
        }
    }
    __syncthreads();   // k_s, q_s dead

    // ---- epilogue: scaled+biased logits -> p_s; V transpose -> vT ----
    {
        const int wm = (warp & 1) * 32, wn = (warp >> 1) * 32;
#pragma unroll
        for (int mt = 0; mt < 2; mt++) {
            const int row0 = wm + mt * 16 + r;
            const int row1 = row0 + 8;
#pragma unroll
            for (int nt = 0; nt < 4; nt++) {
                const int col = wn + nt * 8 + cI * 2;
                if (row0 < WA_) {
                    p_s[row0 * 132 + col]     = fmaf(cq[mt][nt][0], scale, rpbv[mt][nt][0].x);
                    p_s[row0 * 132 + col + 1] = fmaf(cq[mt][nt][1], scale, rpbv[mt][nt][0].y);
                }
                if (row1 < WA_) {
                    p_s[row1 * 132 + col]     = fmaf(cq[mt][nt][2], scale, rpbv[mt][nt][1].x);
                    p_s[row1 * 132 + col + 1] = fmaf(cq[mt][nt][3], scale, rpbv[mt][nt][1].y);
                }
            }
        }
        // zero fp16 P pad rows (rows WA_..63, 68 words per row)
        for (int idx = tid; idx < (64 - WA_) * 68; idx += 256) {
            int row = WA_ + idx / 68, wrd = idx % 68;
            *(uint32_t*)(p_base + row * 528 + wrd * 4) = 0u;
        }

        union { uint4 u[2]; __half hl[16]; } vv;
        vv.u[0] = vu0; vv.u[1] = vu1;
#pragma unroll
        for (int q = 0; q < 16; q++)
            vT_s[(half16 + q) * 136 + j] = vv.hl[q];
    }
    __syncthreads();

    // ---- softmax (pure smem + shfl + exp) -> write fp16 P in-place ----
    for (int i = warp; i < WA_; i += 8) {
        float x0 = p_s[i * 132 + lane];
        float x1 = p_s[i * 132 + lane + 32];
        float x2 = p_s[i * 132 + lane + 64];
        float x3 = p_s[i * 132 + lane + 96];
        float m = fmaxf(fmaxf(x0, x1), fmaxf(x2, x3));
#pragma unroll
        for (int off = 16; off; off >>= 1) m = fmaxf(m, __shfl_xor_sync(0xffffffffu, m, off));
        float e0 = __expf(x0 - m), e1 = __expf(x1 - m);
        float e2 = __expf(x2 - m), e3 = __expf(x3 - m);
        float s = e0 + e1 + e2 + e3;
#pragma unroll
        for (int off = 16; off; off >>= 1) s += __shfl_xor_sync(0xffffffffu, s, off);
        __half* ph = (__half*)(p_base + i * 528);
        ph[lane]      = __float2half(e0);
        ph[lane + 32] = __float2half(e1);
        ph[lane + 64] = __float2half(e2);
        ph[lane + 96] = __float2half(e3);
        if (lane == 0) inv_s[i] = 1.f / s;
    }
    __syncthreads();

    // ---- PV: M=64 N=32 K=128 fp16, ldmatrix; fp16 output ----
    {
        const int wm = (warp >> 1) * 16, wn = (warp & 1) * 16;
        float c[2][4];
#pragma unroll
        for (int nt = 0; nt < 2; nt++)
#pragma unroll
            for (int f = 0; f < 4; f++) c[nt][f] = 0.f;

#pragma unroll
        for (int k16 = 0; k16 < KV_; k16 += 16) {
            uint32_t a0, a1, a2, a3;
            {
                uint32_t ad = sh_addr(p_base + (wm + a_row) * 528 + (k16 + a_koff) * 2);
                LDSM_X4(a0, a1, a2, a3, ad);
            }
            uint32_t bfr[2][2];
            {
                uint32_t ad = sh_addr(&vT_s[(wn + b_row) * 136 + k16 + b_koff]);
                LDSM_X4(bfr[0][0], bfr[0][1], bfr[1][0], bfr[1][1], ad);
            }
#pragma unroll
            for (int nt = 0; nt < 2; nt++)
                MMA_F16(c[nt][0], c[nt][1], c[nt][2], c[nt][3],
                        a0, a1, a2, a3, bfr[nt][0], bfr[nt][1]);
        }

        const int row0 = wm + r, row1 = wm + r + 8;
#pragma unroll
        for (int nt = 0; nt < 2; nt++) {
            const int col = wn + nt * 8 + cI * 2;
            if (row0 < WA_) {
                float inv = inv_s[row0];
                uint32_t o = h2bits(c[nt][0] * inv, c[nt][1] * inv);
                *(uint32_t*)&attn_out[(((size_t)(b * NQ_ + w) * WA_) + row0) * C_ + h * HD_ + col] = o;
            }
            if (row1 < WA_) {
                float inv = inv_s[row1];
                uint32_t o = h2bits(c[nt][2] * inv, c[nt][3] * inv);
                *(uint32_t*)&attn_out[(((size_t)(b * NQ_ + w) * WA_) + row1) * C_ + h * HD_ + col] = o;
            }
        }
    }
}

// ============================================================
// launch
// ============================================================
extern "C" void kernel_launch(void* const* d_in, const int* in_sizes, int n_in,
                              void* d_out, int out_size)
{
    const float* x0      = (const float*)d_in[0];
    const float* x1      = (const float*)d_in[1];
    const float* qkv_w   = (const float*)d_in[2];
    const float* qkv_b   = (const float*)d_in[3];
    const float* proj_w  = (const float*)d_in[4];
    const float* proj_b  = (const float*)d_in[5];
    const float* rpb0_w1 = (const float*)d_in[6];
    const float* rpb0_b1 = (const float*)d_in[7];
    const float* rpb0_w2 = (const float*)d_in[8];
    const float* rpb0_b2 = (const float*)d_in[9];
    const float* rpb1_w1 = (const float*)d_in[10];
    const float* rpb1_b1 = (const float*)d_in[11];
    const float* rpb1_w2 = (const float*)d_in[12];
    const float* rpb1_b2 = (const float*)d_in[13];
    const float* coords0 = (const float*)d_in[14];
    const float* coords1 = (const float*)d_in[15];
    const int*   idx0    = (const int*)d_in[16];
    const int*   idx1    = (const int*)d_in[17];
    float* out = (float*)d_out;

    __half *qkv0, *qkv1, *rpb, *attn_out;
    cudaGetSymbolAddress((void**)&qkv0, g_qkv0);
    cudaGetSymbolAddress((void**)&qkv1, g_qkv1);
    cudaGetSymbolAddress((void**)&rpb, g_rpb);
    cudaGetSymbolAddress((void**)&attn_out, g_attn_out);

    cudaFuncSetAttribute(attn_mma, cudaFuncAttributeMaxDynamicSharedMemorySize, SMEM_ATTN);

    gemm_f16<float, __half><<<dim3(M0_ / 128, 384 / 128), 256>>>(x0, qkv_w, qkv_b, qkv0, M0_, 384, 128);
    gemm_f16<float, __half><<<dim3(M1_ / 128, 384 / 128), 256>>>(x1, qkv_w, qkv_b, qkv1, M1_, 384, 128);
    rpb_kernel<<<(NQ_ * WA_ * KV_ + 255) / 256, 256>>>(
        coords0, coords1,
        rpb0_w1, rpb0_b1, rpb0_w2, rpb0_b2,
        rpb1_w1, rpb1_b1, rpb1_w2, rpb1_b2, rpb);
    attn_mma<<<dim3(NQ_, B_, H_), 256, SMEM_ATTN>>>(idx0, idx1, rpb, qkv0, qkv1, attn_out);
    gemm_f16<__half, float><<<dim3(M0_ / 128, C_ / 128), 256>>>(attn_out, proj_w, proj_b, out, M0_, C_, 128);
}

// round 12
// speedup vs baseline: 1.2295x; 1.2295x over previous
#include <cuda_runtime.h>
#include <cuda_fp16.h>
#include <cstdint>
#include <cstring>

#define B_   32
#define RES_ 56
#define C_   128
#define H_   4
#define HD_  32
#define WS_  7
#define NW_  8
#define NQ_  64
#define WA_  49
#define TOPK_ 64
#define KV_  128
#define P_   3136
#define M0_  (B_*P_)
#define M1_  (B_*NQ_)

__device__ __half g_qkv0[(size_t)M0_ * 384];
__device__ __half g_qkv1[(size_t)M1_ * 384];
__device__ float  g_rpb[(size_t)NQ_ * H_ * WA_ * KV_];
__device__ __half g_attn_out[(size_t)M0_ * C_];

#define MMA_F16(C0,C1,C2,C3,A0,A1,A2,A3,B0,B1) \
    asm volatile("mma.sync.aligned.m16n8k16.row.col.f32.f16.f16.f32 " \
        "{%0,%1,%2,%3},{%4,%5,%6,%7},{%8,%9},{%0,%1,%2,%3};" \
        : "+f"(C0), "+f"(C1), "+f"(C2), "+f"(C3) \
        : "r"(A0), "r"(A1), "r"(A2), "r"(A3), "r"(B0), "r"(B1))

#define LDSM_X4(R0,R1,R2,R3,ADDR) \
    asm volatile("ldmatrix.sync.aligned.m8n8.x4.shared.b16 {%0,%1,%2,%3}, [%4];" \
        : "=r"(R0), "=r"(R1), "=r"(R2), "=r"(R3) : "r"(ADDR))

__device__ __forceinline__ uint32_t sh_addr(const void* p) {
    return (uint32_t)__cvta_generic_to_shared(p);
}
__device__ __forceinline__ uint4 f4_to_h8(float4 a, float4 b) {
    __half2 h0 = __floats2half2_rn(a.x, a.y);
    __half2 h1 = __floats2half2_rn(a.z, a.w);
    __half2 h2 = __floats2half2_rn(b.x, b.y);
    __half2 h3 = __floats2half2_rn(b.z, b.w);
    uint4 u = {*(uint32_t*)&h0, *(uint32_t*)&h1, *(uint32_t*)&h2, *(uint32_t*)&h3};
    return u;
}
__device__ __forceinline__ uint32_t h2bits(float a, float b) {
    __half2 h = __floats2half2_rn(a, b);
    return *(uint32_t*)&h;
}

// ============================================================
// FP16-mma GEMM: C[M,N] = A[M,K]*B[N,K]^T + bias[N]
// ============================================================
template <typename TA, typename TO>
__global__ __launch_bounds__(256) void gemm_f16(
    const TA* __restrict__ A, const float* __restrict__ Bm,
    const float* __restrict__ bias, TO* __restrict__ C,
    int M, int N, int K)
{
    __shared__ __half As[128 * 40];
    __shared__ __half Bs[128 * 40];

    const int tid = threadIdx.x;
    const int m0 = blockIdx.x * 128;
    const int n0 = blockIdx.y * 128;
    const int warp = tid >> 5, lane = tid & 31;
    const int wm = (warp >> 2) * 64;
    const int wn = (warp & 3) * 32;
    const int r = lane >> 2;
    const int cI = lane & 3;

    const int a_row  = lane & 15;
    const int a_koff = (lane >> 4) * 8;
    const int b_row  = (lane & 7) + (lane >> 4) * 8;
    const int b_koff = ((lane >> 3) & 1) * 8;

    float c[4][4][4];
#pragma unroll
    for (int mt = 0; mt < 4; mt++)
#pragma unroll
        for (int nt = 0; nt < 4; nt++)
#pragma unroll
            for (int f = 0; f < 4; f++) c[mt][nt][f] = 0.f;

    const int lr = tid >> 1;
    const int ls = (tid & 1) * 16;
    const TA*    Arow = A  + (size_t)(m0 + lr) * K + ls;
    const float* Brow = Bm + (size_t)(n0 + lr) * K + ls;

    float4 ra[4];
    uint4  rah[2];
    float4 rb[4];
    if constexpr (sizeof(TA) == 4) {
#pragma unroll
        for (int q = 0; q < 4; q++) ra[q] = *(const float4*)((const float*)Arow + q * 4);
    } else {
        rah[0] = *(const uint4*)((const __half*)Arow);
        rah[1] = *(const uint4*)((const __half*)Arow + 8);
    }
#pragma unroll
    for (int q = 0; q < 4; q++) rb[q] = *(const float4*)(Brow + q * 4);

    for (int k0 = 0; k0 < K; k0 += 32) {
        if constexpr (sizeof(TA) == 4) {
            *(uint4*)&As[lr * 40 + ls]     = f4_to_h8(ra[0], ra[1]);
            *(uint4*)&As[lr * 40 + ls + 8] = f4_to_h8(ra[2], ra[3]);
        } else {
            *(uint4*)&As[lr * 40 + ls]     = rah[0];
            *(uint4*)&As[lr * 40 + ls + 8] = rah[1];
        }
        *(uint4*)&Bs[lr * 40 + ls]     = f4_to_h8(rb[0], rb[1]);
        *(uint4*)&Bs[lr * 40 + ls + 8] = f4_to_h8(rb[2], rb[3]);
        __syncthreads();

        if (k0 + 32 < K) {
            if constexpr (sizeof(TA) == 4) {
#pragma unroll
                for (int q = 0; q < 4; q++)
                    ra[q] = *(const float4*)((const float*)Arow + k0 + 32 + q * 4);
            } else {
                rah[0] = *(const uint4*)((const __half*)Arow + k0 + 32);
                rah[1] = *(const uint4*)((const __half*)Arow + k0 + 40);
            }
#pragma unroll
            for (int q = 0; q < 4; q++)
                rb[q] = *(const float4*)(Brow + k0 + 32 + q * 4);
        }

#pragma unroll
        for (int k16 = 0; k16 < 32; k16 += 16) {
            uint32_t a[4][4], b[4][2];
#pragma unroll
            for (int mt = 0; mt < 4; mt++) {
                uint32_t ad = sh_addr(&As[(wm + mt * 16 + a_row) * 40 + k16 + a_koff]);
                LDSM_X4(a[mt][0], a[mt][1], a[mt][2], a[mt][3], ad);
            }
#pragma unroll
            for (int np = 0; np < 2; np++) {
                uint32_t ad = sh_addr(&Bs[(wn + np * 16 + b_row) * 40 + k16 + b_koff]);
                LDSM_X4(b[2 * np][0], b[2 * np][1], b[2 * np + 1][0], b[2 * np + 1][1], ad);
            }
#pragma unroll
            for (int mt = 0; mt < 4; mt++)
#pragma unroll
                for (int nt = 0; nt < 4; nt++)
                    MMA_F16(c[mt][nt][0], c[mt][nt][1], c[mt][nt][2], c[mt][nt][3],
                            a[mt][0], a[mt][1], a[mt][2], a[mt][3],
                            b[nt][0], b[nt][1]);
        }
        __syncthreads();
    }

#pragma unroll
    for (int mt = 0; mt < 4; mt++) {
        const int row = m0 + wm + mt * 16 + r;
#pragma unroll
        for (int nt = 0; nt < 4; nt++) {
            const int col = n0 + wn + nt * 8 + cI * 2;
            float2 bb = *(const float2*)&bias[col];
            if constexpr (sizeof(TO) == 4) {
                float2 o0 = {c[mt][nt][0] + bb.x, c[mt][nt][1] + bb.y};
                float2 o1 = {c[mt][nt][2] + bb.x, c[mt][nt][3] + bb.y};
                *(float2*)&((float*)C)[(size_t)row * N + col]       = o0;
                *(float2*)&((float*)C)[(size_t)(row + 8) * N + col] = o1;
            } else {
                uint32_t o0 = h2bits(c[mt][nt][0] + bb.x, c[mt][nt][1] + bb.y);
                uint32_t o1 = h2bits(c[mt][nt][2] + bb.x, c[mt][nt][3] + bb.y);
                *(uint32_t*)&((__half*)C)[(size_t)row * N + col]       = o0;
                *(uint32_t*)&((__half*)C)[(size_t)(row + 8) * N + col] = o1;
            }
        }
    }
}

// ============================================================
// RPB MLP precompute (fp32 table)
// ============================================================
__global__ void rpb_kernel(
    const float* __restrict__ coords0, const float* __restrict__ coords1,
    const float* __restrict__ w1a, const float* __restrict__ b1a,
    const float* __restrict__ w2a, const float* __restrict__ b2a,
    const float* __restrict__ w1b, const float* __restrict__ b1b,
    const float* __restrict__ w2b, const float* __restrict__ b2b,
    float* __restrict__ rpb)
{
    int t = blockIdx.x * blockDim.x + threadIdx.x;
    const int TOT = NQ_ * WA_ * KV_;
    if (t >= TOT) return;
    int j = t & 127;
    int i = (t >> 7) % WA_;
    int w = t / (KV_ * WA_);

    const float *co, *w1, *b1, *w2, *b2;
    int jj;
    if (j < TOPK_) { co = coords0; jj = j;          w1 = w1a; b1 = b1a; w2 = w2a; b2 = b2a; }
    else           { co = coords1; jj = j - TOPK_;  w1 = w1b; b1 = b1b; w2 = w2b; b2 = b2b; }

    size_t cbase = ((size_t)(w * WA_ + i) * TOPK_ + jj) * 2;
    float cy = co[cbase + 0];
    float cx = co[cbase + 1];

    float o0 = b2[0], o1 = b2[1], o2 = b2[2], o3 = b2[3];
#pragma unroll
    for (int tt = 0; tt < HD_; tt++) {
        float hsum = fmaxf(fmaf(w1[tt * 2], cy, fmaf(w1[tt * 2 + 1], cx, b1[tt])), 0.f);
        o0 = fmaf(w2[0 * HD_ + tt], hsum, o0);
        o1 = fmaf(w2[1 * HD_ + tt], hsum, o1);
        o2 = fmaf(w2[2 * HD_ + tt], hsum, o2);
        o3 = fmaf(w2[3 * HD_ + tt], hsum, o3);
    }
    size_t base = ((size_t)(w * H_) * WA_ + i) * KV_ + j;
    const size_t hstride = (size_t)WA_ * KV_;
    rpb[base + 0 * hstride] = o0;
    rpb[base + 1 * hstride] = o1;
    rpb[base + 2 * hstride] = o2;
    rpb[base + 3 * hstride] = o3;
}

// ============================================================
// FP16 tensor-core attention (44288 B smem, 5 CTAs/SM)
// rpb in softmax (coalesced), depth-1 pipelined loads
// ============================================================
#define SMEM_ATTN 44288

__global__ __launch_bounds__(256, 5) void attn_mma(
    const int* __restrict__ idx0, const int* __restrict__ idx1,
    const float* __restrict__ rpb,
    const __half* __restrict__ qkv0, const __half* __restrict__ qkv1,
    __half* __restrict__ attn_out)
{
    extern __shared__ char smem_raw[];
    __half* k_s  = (__half*)(smem_raw);
    __half* vT_s = (__half*)(smem_raw);                 // alias after QK
    float*  p_s  = (float*) (smem_raw + 10240);
    __half* q_s  = (__half*)(smem_raw + 10240);         // alias (dead after QK)
    float*  inv_s= (float*) (smem_raw + 44032);
    char*   p_base = smem_raw + 10240;

    const int w = blockIdx.x, b = blockIdx.y, h = blockIdx.z;
    const int tid = threadIdx.x;
    const int warp = tid >> 5, lane = tid & 31;
    const int r = lane >> 2, cI = lane & 3;

    const int a_row  = lane & 15;
    const int a_koff = (lane >> 4) * 8;
    const int b_row  = (lane & 7) + (lane >> 4) * 8;
    const int b_koff = ((lane >> 3) & 1) * 8;

    // ---- gather K: 2 threads per key row ----
    const int j = tid >> 1;
    const int half16 = (tid & 1) * 16;
    const __half* basep;
    if (j < TOPK_) basep = qkv0 + ((size_t)b * P_ + idx0[w * TOPK_ + j]) * 384;
    else           basep = qkv1 + ((size_t)b * NQ_ + idx1[w * TOPK_ + (j - TOPK_)]) * 384;

    {
        const uint4* kp = (const uint4*)(basep + C_ + h * HD_ + half16);
        uint4 k0 = kp[0], k1 = kp[1];
        *(uint4*)&k_s[j * 40 + half16]     = k0;
        *(uint4*)&k_s[j * 40 + half16 + 8] = k1;
    }

    // ---- load Q (49 rows, pad to 64): 8 halves per thread ----
    const int wy = w >> 3, wx = w & 7;
    {
        int i = tid >> 2, d = (tid & 3) * 8;
        uint4 val = {0u, 0u, 0u, 0u};
        if (i < WA_) {
            int pos = (wy * WS_ + i / WS_) * RES_ + wx * WS_ + i % WS_;
            val = *(const uint4*)(qkv0 + ((size_t)b * P_ + pos) * 384 + h * HD_ + d);
        }
        *(uint4*)&q_s[i * 40 + d] = val;
    }
    __syncthreads();

    // ---- QK: M=64 N=128 K=32 ----
    float cq[2][4][4];
    {
        const int wm = (warp & 1) * 32, wn = (warp >> 1) * 32;
#pragma unroll
        for (int mt = 0; mt < 2; mt++)
#pragma unroll
            for (int nt = 0; nt < 4; nt++)
#pragma unroll
                for (int f = 0; f < 4; f++) cq[mt][nt][f] = 0.f;

#pragma unroll
        for (int k16 = 0; k16 < 32; k16 += 16) {
            uint32_t a[2][4], bb[4][2];
#pragma unroll
            for (int mt = 0; mt < 2; mt++) {
                uint32_t ad = sh_addr(&q_s[(wm + mt * 16 + a_row) * 40 + k16 + a_koff]);
                LDSM_X4(a[mt][0], a[mt][1], a[mt][2], a[mt][3], ad);
            }
#pragma unroll
            for (int np = 0; np < 2; np++) {
                uint32_t ad = sh_addr(&k_s[(wn + np * 16 + b_row) * 40 + k16 + b_koff]);
                LDSM_X4(bb[2 * np][0], bb[2 * np][1], bb[2 * np + 1][0], bb[2 * np + 1][1], ad);
            }
#pragma unroll
            for (int mt = 0; mt < 2; mt++)
#pragma unroll
                for (int nt = 0; nt < 4; nt++)
                    MMA_F16(cq[mt][nt][0], cq[mt][nt][1], cq[mt][nt][2], cq[mt][nt][3],
                            a[mt][0], a[mt][1], a[mt][2], a[mt][3],
                            bb[nt][0], bb[nt][1]);
        }
    }

    // ---- issue V gather loads (fp16, no smem dependence) ----
    uint4 vu0, vu1;
    {
        const uint4* vp = (const uint4*)(basep + 2 * C_ + h * HD_ + half16);
        vu0 = vp[0]; vu1 = vp[1];
    }
    __syncthreads();   // k_s, q_s dead

    // ---- epilogue: raw logits -> p_s (fp32); V transpose -> vT (fp16) ----
    {
        const int wm = (warp & 1) * 32, wn = (warp >> 1) * 32;
#pragma unroll
        for (int mt = 0; mt < 2; mt++) {
            const int row0 = wm + mt * 16 + r;
            const int row1 = row0 + 8;
#pragma unroll
            for (int nt = 0; nt < 4; nt++) {
                const int col = wn + nt * 8 + cI * 2;
                if (row0 < WA_) {
                    p_s[row0 * 132 + col]     = cq[mt][nt][0];
                    p_s[row0 * 132 + col + 1] = cq[mt][nt][1];
                }
                if (row1 < WA_) {
                    p_s[row1 * 132 + col]     = cq[mt][nt][2];
                    p_s[row1 * 132 + col + 1] = cq[mt][nt][3];
                }
            }
        }
        // zero fp16 P pad rows (rows WA_..63, 68 words per row)
        for (int idx = tid; idx < (64 - WA_) * 68; idx += 256) {
            int row = WA_ + idx / 68, wrd = idx % 68;
            *(uint32_t*)(p_base + row * 528 + wrd * 4) = 0u;
        }

        union { uint4 u[2]; __half hl[16]; } vv;
        vv.u[0] = vu0; vv.u[1] = vu1;
#pragma unroll
        for (int q = 0; q < 16; q++)
            vT_s[(half16 + q) * 136 + j] = vv.hl[q];
    }
    __syncthreads();

    // ---- softmax (fused scale+rpb, coalesced rpb reads, pipelined) ----
    const float scale = 0.17677669529663687f;
    const float* rpb_wh = rpb + (size_t)(w * H_ + h) * WA_ * KV_;
    {
        int i = warp;
        float r0 = 0.f, r1 = 0.f, r2 = 0.f, r3 = 0.f;
        if (i < WA_) {
            const float* rrow = rpb_wh + i * KV_;
            r0 = rrow[lane]; r1 = rrow[lane + 32];
            r2 = rrow[lane + 64]; r3 = rrow[lane + 96];
        }
        while (i < WA_) {
            const int inext = i + 8;
            float n0, n1, n2, n3;
            if (inext < WA_) {
                const float* rrow = rpb_wh + inext * KV_;
                n0 = rrow[lane]; n1 = rrow[lane + 32];
                n2 = rrow[lane + 64]; n3 = rrow[lane + 96];
            }
            float x0 = fmaf(p_s[i * 132 + lane],      scale, r0);
            float x1 = fmaf(p_s[i * 132 + lane + 32], scale, r1);
            float x2 = fmaf(p_s[i * 132 + lane + 64], scale, r2);
            float x3 = fmaf(p_s[i * 132 + lane + 96], scale, r3);
            float m = fmaxf(fmaxf(x0, x1), fmaxf(x2, x3));
#pragma unroll
            for (int off = 16; off; off >>= 1) m = fmaxf(m, __shfl_xor_sync(0xffffffffu, m, off));
            float e0 = __expf(x0 - m), e1 = __expf(x1 - m);
            float e2 = __expf(x2 - m), e3 = __expf(x3 - m);
            float s = e0 + e1 + e2 + e3;
#pragma unroll
            for (int off = 16; off; off >>= 1) s += __shfl_xor_sync(0xffffffffu, s, off);
            __half* ph = (__half*)(p_base + i * 528);
            ph[lane]      = __float2half(e0);
            ph[lane + 32] = __float2half(e1);
            ph[lane + 64] = __float2half(e2);
            ph[lane + 96] = __float2half(e3);
            if (lane == 0) inv_s[i] = 1.f / s;
            if (inext < WA_) { r0 = n0; r1 = n1; r2 = n2; r3 = n3; }
            i = inext;
        }
    }
    __syncthreads();

    // ---- PV: M=64 N=32 K=128 fp16, ldmatrix; fp16 output ----
    {
        const int wm = (warp >> 1) * 16, wn = (warp & 1) * 16;
        float c[2][4];
#pragma unroll
        for (int nt = 0; nt < 2; nt++)
#pragma unroll
            for (int f = 0; f < 4; f++) c[nt][f] = 0.f;

#pragma unroll
        for (int k16 = 0; k16 < KV_; k16 += 16) {
            uint32_t a0, a1, a2, a3;
            {
                uint32_t ad = sh_addr(p_base + (wm + a_row) * 528 + (k16 + a_koff) * 2);
                LDSM_X4(a0, a1, a2, a3, ad);
            }
            uint32_t bfr[2][2];
            {
                uint32_t ad = sh_addr(&vT_s[(wn + b_row) * 136 + k16 + b_koff]);
                LDSM_X4(bfr[0][0], bfr[0][1], bfr[1][0], bfr[1][1], ad);
            }
#pragma unroll
            for (int nt = 0; nt < 2; nt++)
                MMA_F16(c[nt][0], c[nt][1], c[nt][2], c[nt][3],
                        a0, a1, a2, a3, bfr[nt][0], bfr[nt][1]);
        }

        const int row0 = wm + r, row1 = wm + r + 8;
#pragma unroll
        for (int nt = 0; nt < 2; nt++) {
            const int col = wn + nt * 8 + cI * 2;
            if (row0 < WA_) {
                float inv = inv_s[row0];
                uint32_t o = h2bits(c[nt][0] * inv, c[nt][1] * inv);
                *(uint32_t*)&attn_out[(((size_t)(b * NQ_ + w) * WA_) + row0) * C_ + h * HD_ + col] = o;
            }
            if (row1 < WA_) {
                float inv = inv_s[row1];
                uint32_t o = h2bits(c[nt][2] * inv, c[nt][3] * inv);
                *(uint32_t*)&attn_out[(((size_t)(b * NQ_ + w) * WA_) + row1) * C_ + h * HD_ + col] = o;
            }
        }
    }
}

// ============================================================
// launch
// ============================================================
extern "C" void kernel_launch(void* const* d_in, const int* in_sizes, int n_in,
                              void* d_out, int out_size)
{
    const float* x0      = (const float*)d_in[0];
    const float* x1      = (const float*)d_in[1];
    const float* qkv_w   = (const float*)d_in[2];
    const float* qkv_b   = (const float*)d_in[3];
    const float* proj_w  = (const float*)d_in[4];
    const float* proj_b  = (const float*)d_in[5];
    const float* rpb0_w1 = (const float*)d_in[6];
    const float* rpb0_b1 = (const float*)d_in[7];
    const float* rpb0_w2 = (const float*)d_in[8];
    const float* rpb0_b2 = (const float*)d_in[9];
    const float* rpb1_w1 = (const float*)d_in[10];
    const float* rpb1_b1 = (const float*)d_in[11];
    const float* rpb1_w2 = (const float*)d_in[12];
    const float* rpb1_b2 = (const float*)d_in[13];
    const float* coords0 = (const float*)d_in[14];
    const float* coords1 = (const float*)d_in[15];
    const int*   idx0    = (const int*)d_in[16];
    const int*   idx1    = (const int*)d_in[17];
    float* out = (float*)d_out;

    __half *qkv0, *qkv1, *attn_out;
    float *rpb;
    cudaGetSymbolAddress((void**)&qkv0, g_qkv0);
    cudaGetSymbolAddress((void**)&qkv1, g_qkv1);
    cudaGetSymbolAddress((void**)&rpb, g_rpb);
    cudaGetSymbolAddress((void**)&attn_out, g_attn_out);

    cudaFuncSetAttribute(attn_mma, cudaFuncAttributeMaxDynamicSharedMemorySize, SMEM_ATTN);

    gemm_f16<float, __half><<<dim3(M0_ / 128, 384 / 128), 256>>>(x0, qkv_w, qkv_b, qkv0, M0_, 384, 128);
    gemm_f16<float, __half><<<dim3(M1_ / 128, 384 / 128), 256>>>(x1, qkv_w, qkv_b, qkv1, M1_, 384, 128);
    rpb_kernel<<<(NQ_ * WA_ * KV_ + 255) / 256, 256>>>(
        coords0, coords1,
        rpb0_w1, rpb0_b1, rpb0_w2, rpb0_b2,
        rpb1_w1, rpb1_b1, rpb1_w2, rpb1_b2, rpb);
    attn_mma<<<dim3(NQ_, B_, H_), 256, SMEM_ATTN>>>(idx0, idx1, rpb, qkv0, qkv1, attn_out);
    gemm_f16<__half, float><<<dim3(M0_ / 128, C_ / 128), 256>>>(attn_out, proj_w, proj_b, out, M0_, C_, 128);
}

// round 13
// speedup vs baseline: 1.2392x; 1.0079x over previous
#include <cuda_runtime.h>
#include <cuda_fp16.h>
#include <cstdint>
#include <cstring>

#define B_   32
#define RES_ 56
#define C_   128
#define H_   4
#define HD_  32
#define WS_  7
#define NW_  8
#define NQ_  64
#define WA_  49
#define TOPK_ 64
#define KV_  128
#define P_   3136
#define M0_  (B_*P_)
#define M1_  (B_*NQ_)

__device__ __half g_qkv0[(size_t)M0_ * 384];
__device__ __half g_qkv1[(size_t)M1_ * 384];
__device__ float  g_rpb[(size_t)NQ_ * H_ * WA_ * KV_];
__device__ __half g_attn_out[(size_t)M0_ * C_];

#define MMA_F16(C0,C1,C2,C3,A0,A1,A2,A3,B0,B1) \
    asm volatile("mma.sync.aligned.m16n8k16.row.col.f32.f16.f16.f32 " \
        "{%0,%1,%2,%3},{%4,%5,%6,%7},{%8,%9},{%0,%1,%2,%3};" \
        : "+f"(C0), "+f"(C1), "+f"(C2), "+f"(C3) \
        : "r"(A0), "r"(A1), "r"(A2), "r"(A3), "r"(B0), "r"(B1))

#define LDSM_X4(R0,R1,R2,R3,ADDR) \
    asm volatile("ldmatrix.sync.aligned.m8n8.x4.shared.b16 {%0,%1,%2,%3}, [%4];" \
        : "=r"(R0), "=r"(R1), "=r"(R2), "=r"(R3) : "r"(ADDR))

#define LDSM_X4_T(R0,R1,R2,R3,ADDR) \
    asm volatile("ldmatrix.sync.aligned.m8n8.x4.trans.shared.b16 {%0,%1,%2,%3}, [%4];" \
        : "=r"(R0), "=r"(R1), "=r"(R2), "=r"(R3) : "r"(ADDR))

__device__ __forceinline__ uint32_t sh_addr(const void* p) {
    return (uint32_t)__cvta_generic_to_shared(p);
}
__device__ __forceinline__ uint4 f4_to_h8(float4 a, float4 b) {
    __half2 h0 = __floats2half2_rn(a.x, a.y);
    __half2 h1 = __floats2half2_rn(a.z, a.w);
    __half2 h2 = __floats2half2_rn(b.x, b.y);
    __half2 h3 = __floats2half2_rn(b.z, b.w);
    uint4 u = {*(uint32_t*)&h0, *(uint32_t*)&h1, *(uint32_t*)&h2, *(uint32_t*)&h3};
    return u;
}
__device__ __forceinline__ uint32_t h2bits(float a, float b) {
    __half2 h = __floats2half2_rn(a, b);
    return *(uint32_t*)&h;
}

// ============================================================
// FP16-mma GEMM: C[M,N] = A[M,K]*B[N,K]^T + bias[N]
// ============================================================
template <typename TA, typename TO>
__global__ __launch_bounds__(256) void gemm_f16(
    const TA* __restrict__ A, const float* __restrict__ Bm,
    const float* __restrict__ bias, TO* __restrict__ C,
    int M, int N, int K)
{
    __shared__ __half As[128 * 40];
    __shared__ __half Bs[128 * 40];

    const int tid = threadIdx.x;
    const int m0 = blockIdx.x * 128;
    const int n0 = blockIdx.y * 128;
    const int warp = tid >> 5, lane = tid & 31;
    const int wm = (warp >> 2) * 64;
    const int wn = (warp & 3) * 32;
    const int r = lane >> 2;
    const int cI = lane & 3;

    const int a_row  = lane & 15;
    const int a_koff = (lane >> 4) * 8;
    const int b_row  = (lane & 7) + (lane >> 4) * 8;
    const int b_koff = ((lane >> 3) & 1) * 8;

    float c[4][4][4];
#pragma unroll
    for (int mt = 0; mt < 4; mt++)
#pragma unroll
        for (int nt = 0; nt < 4; nt++)
#pragma unroll
            for (int f = 0; f < 4; f++) c[mt][nt][f] = 0.f;

    const int lr = tid >> 1;
    const int ls = (tid & 1) * 16;
    const TA*    Arow = A  + (size_t)(m0 + lr) * K + ls;
    const float* Brow = Bm + (size_t)(n0 + lr) * K + ls;

    float4 ra[4];
    uint4  rah[2];
    float4 rb[4];
    if constexpr (sizeof(TA) == 4) {
#pragma unroll
        for (int q = 0; q < 4; q++) ra[q] = *(const float4*)((const float*)Arow + q * 4);
    } else {
        rah[0] = *(const uint4*)((const __half*)Arow);
        rah[1] = *(const uint4*)((const __half*)Arow + 8);
    }
#pragma unroll
    for (int q = 0; q < 4; q++) rb[q] = *(const float4*)(Brow + q * 4);

    for (int k0 = 0; k0 < K; k0 += 32) {
        if constexpr (sizeof(TA) == 4) {
            *(uint4*)&As[lr * 40 + ls]     = f4_to_h8(ra[0], ra[1]);
            *(uint4*)&As[lr * 40 + ls + 8] = f4_to_h8(ra[2], ra[3]);
        } else {
            *(uint4*)&As[lr * 40 + ls]     = rah[0];
            *(uint4*)&As[lr * 40 + ls + 8] = rah[1];
        }
        *(uint4*)&Bs[lr * 40 + ls]     = f4_to_h8(rb[0], rb[1]);
        *(uint4*)&Bs[lr * 40 + ls + 8] = f4_to_h8(rb[2], rb[3]);
        __syncthreads();

        if (k0 + 32 < K) {
            if constexpr (sizeof(TA) == 4) {
#pragma unroll
                for (int q = 0; q < 4; q++)
                    ra[q] = *(const float4*)((const float*)Arow + k0 + 32 + q * 4);
            } else {
                rah[0] = *(const uint4*)((const __half*)Arow + k0 + 32);
                rah[1] = *(const uint4*)((const __half*)Arow + k0 + 40);
            }
#pragma unroll
            for (int q = 0; q < 4; q++)
                rb[q] = *(const float4*)(Brow + k0 + 32 + q * 4);
        }

#pragma unroll
        for (int k16 = 0; k16 < 32; k16 += 16) {
            uint32_t a[4][4], b[4][2];
#pragma unroll
            for (int mt = 0; mt < 4; mt++) {
                uint32_t ad = sh_addr(&As[(wm + mt * 16 + a_row) * 40 + k16 + a_koff]);
                LDSM_X4(a[mt][0], a[mt][1], a[mt][2], a[mt][3], ad);
            }
#pragma unroll
            for (int np = 0; np < 2; np++) {
                uint32_t ad = sh_addr(&Bs[(wn + np * 16 + b_row) * 40 + k16 + b_koff]);
                LDSM_X4(b[2 * np][0], b[2 * np][1], b[2 * np + 1][0], b[2 * np + 1][1], ad);
            }
#pragma unroll
            for (int mt = 0; mt < 4; mt++)
#pragma unroll
                for (int nt = 0; nt < 4; nt++)
                    MMA_F16(c[mt][nt][0], c[mt][nt][1], c[mt][nt][2], c[mt][nt][3],
                            a[mt][0], a[mt][1], a[mt][2], a[mt][3],
                            b[nt][0], b[nt][1]);
        }
        __syncthreads();
    }

#pragma unroll
    for (int mt = 0; mt < 4; mt++) {
        const int row = m0 + wm + mt * 16 + r;
#pragma unroll
        for (int nt = 0; nt < 4; nt++) {
            const int col = n0 + wn + nt * 8 + cI * 2;
            float2 bb = *(const float2*)&bias[col];
            if constexpr (sizeof(TO) == 4) {
                float2 o0 = {c[mt][nt][0] + bb.x, c[mt][nt][1] + bb.y};
                float2 o1 = {c[mt][nt][2] + bb.x, c[mt][nt][3] + bb.y};
                *(float2*)&((float*)C)[(size_t)row * N + col]       = o0;
                *(float2*)&((float*)C)[(size_t)(row + 8) * N + col] = o1;
            } else {
                uint32_t o0 = h2bits(c[mt][nt][0] + bb.x, c[mt][nt][1] + bb.y);
                uint32_t o1 = h2bits(c[mt][nt][2] + bb.x, c[mt][nt][3] + bb.y);
                *(uint32_t*)&((__half*)C)[(size_t)row * N + col]       = o0;
                *(uint32_t*)&((__half*)C)[(size_t)(row + 8) * N + col] = o1;
            }
        }
    }
}

// ============================================================
// RPB MLP precompute (fp32 table)
// ============================================================
__global__ void rpb_kernel(
    const float* __restrict__ coords0, const float* __restrict__ coords1,
    const float* __restrict__ w1a, const float* __restrict__ b1a,
    const float* __restrict__ w2a, const float* __restrict__ b2a,
    const float* __restrict__ w1b, const float* __restrict__ b1b,
    const float* __restrict__ w2b, const float* __restrict__ b2b,
    float* __restrict__ rpb)
{
    int t = blockIdx.x * blockDim.x + threadIdx.x;
    const int TOT = NQ_ * WA_ * KV_;
    if (t >= TOT) return;
    int j = t & 127;
    int i = (t >> 7) % WA_;
    int w = t / (KV_ * WA_);

    const float *co, *w1, *b1, *w2, *b2;
    int jj;
    if (j < TOPK_) { co = coords0; jj = j;          w1 = w1a; b1 = b1a; w2 = w2a; b2 = b2a; }
    else           { co = coords1; jj = j - TOPK_;  w1 = w1b; b1 = b1b; w2 = w2b; b2 = b2b; }

    size_t cbase = ((size_t)(w * WA_ + i) * TOPK_ + jj) * 2;
    float cy = co[cbase + 0];
    float cx = co[cbase + 1];

    float o0 = b2[0], o1 = b2[1], o2 = b2[2], o3 = b2[3];
#pragma unroll
    for (int tt = 0; tt < HD_; tt++) {
        float hsum = fmaxf(fmaf(w1[tt * 2], cy, fmaf(w1[tt * 2 + 1], cx, b1[tt])), 0.f);
        o0 = fmaf(w2[0 * HD_ + tt], hsum, o0);
        o1 = fmaf(w2[1 * HD_ + tt], hsum, o1);
        o2 = fmaf(w2[2 * HD_ + tt], hsum, o2);
        o3 = fmaf(w2[3 * HD_ + tt], hsum, o3);
    }
    size_t base = ((size_t)(w * H_) * WA_ + i) * KV_ + j;
    const size_t hstride = (size_t)WA_ * KV_;
    rpb[base + 0 * hstride] = o0;
    rpb[base + 1 * hstride] = o1;
    rpb[base + 2 * hstride] = o2;
    rpb[base + 3 * hstride] = o3;
}

// ============================================================
// FP16 tensor-core attention (44288 B smem, 5 CTAs/SM)
// V untransposed + ldmatrix.trans in PV; float2 epilogue stores
// ============================================================
#define SMEM_ATTN 44288

__global__ __launch_bounds__(256, 5) void attn_mma(
    const int* __restrict__ idx0, const int* __restrict__ idx1,
    const float* __restrict__ rpb,
    const __half* __restrict__ qkv0, const __half* __restrict__ qkv1,
    __half* __restrict__ attn_out)
{
    extern __shared__ char smem_raw[];
    __half* k_s  = (__half*)(smem_raw);                 // [128][40]
    __half* v_s  = (__half*)(smem_raw);                 // alias after QK, [128][40]
    float*  p_s  = (float*) (smem_raw + 10240);
    __half* q_s  = (__half*)(smem_raw + 10240);         // alias (dead after QK)
    float*  inv_s= (float*) (smem_raw + 44032);
    char*   p_base = smem_raw + 10240;

    const int w = blockIdx.x, b = blockIdx.y, h = blockIdx.z;
    const int tid = threadIdx.x;
    const int warp = tid >> 5, lane = tid & 31;
    const int r = lane >> 2, cI = lane & 3;

    const int a_row  = lane & 15;
    const int a_koff = (lane >> 4) * 8;
    const int b_row  = (lane & 7) + (lane >> 4) * 8;
    const int b_koff = ((lane >> 3) & 1) * 8;

    // ---- gather K: 2 threads per key row ----
    const int j = tid >> 1;
    const int half16 = (tid & 1) * 16;
    const __half* basep;
    if (j < TOPK_) basep = qkv0 + ((size_t)b * P_ + idx0[w * TOPK_ + j]) * 384;
    else           basep = qkv1 + ((size_t)b * NQ_ + idx1[w * TOPK_ + (j - TOPK_)]) * 384;

    {
        const uint4* kp = (const uint4*)(basep + C_ + h * HD_ + half16);
        uint4 k0 = kp[0], k1 = kp[1];
        *(uint4*)&k_s[j * 40 + half16]     = k0;
        *(uint4*)&k_s[j * 40 + half16 + 8] = k1;
    }

    // ---- load Q (49 rows, pad to 64): 8 halves per thread ----
    const int wy = w >> 3, wx = w & 7;
    {
        int i = tid >> 2, d = (tid & 3) * 8;
        uint4 val = {0u, 0u, 0u, 0u};
        if (i < WA_) {
            int pos = (wy * WS_ + i / WS_) * RES_ + wx * WS_ + i % WS_;
            val = *(const uint4*)(qkv0 + ((size_t)b * P_ + pos) * 384 + h * HD_ + d);
        }
        *(uint4*)&q_s[i * 40 + d] = val;
    }
    __syncthreads();

    // ---- QK: M=64 N=128 K=32 ----
    float cq[2][4][4];
    {
        const int wm = (warp & 1) * 32, wn = (warp >> 1) * 32;
#pragma unroll
        for (int mt = 0; mt < 2; mt++)
#pragma unroll
            for (int nt = 0; nt < 4; nt++)
#pragma unroll
                for (int f = 0; f < 4; f++) cq[mt][nt][f] = 0.f;

#pragma unroll
        for (int k16 = 0; k16 < 32; k16 += 16) {
            uint32_t a[2][4], bb[4][2];
#pragma unroll
            for (int mt = 0; mt < 2; mt++) {
                uint32_t ad = sh_addr(&q_s[(wm + mt * 16 + a_row) * 40 + k16 + a_koff]);
                LDSM_X4(a[mt][0], a[mt][1], a[mt][2], a[mt][3], ad);
            }
#pragma unroll
            for (int np = 0; np < 2; np++) {
                uint32_t ad = sh_addr(&k_s[(wn + np * 16 + b_row) * 40 + k16 + b_koff]);
                LDSM_X4(bb[2 * np][0], bb[2 * np][1], bb[2 * np + 1][0], bb[2 * np + 1][1], ad);
            }
#pragma unroll
            for (int mt = 0; mt < 2; mt++)
#pragma unroll
                for (int nt = 0; nt < 4; nt++)
                    MMA_F16(cq[mt][nt][0], cq[mt][nt][1], cq[mt][nt][2], cq[mt][nt][3],
                            a[mt][0], a[mt][1], a[mt][2], a[mt][3],
                            bb[nt][0], bb[nt][1]);
        }
    }

    // ---- issue V gather loads (fp16, no smem dependence) ----
    uint4 vu0, vu1;
    {
        const uint4* vp = (const uint4*)(basep + 2 * C_ + h * HD_ + half16);
        vu0 = vp[0]; vu1 = vp[1];
    }
    __syncthreads();   // k_s, q_s dead

    // ---- epilogue: raw logits -> p_s (float2 stores); V rows -> v_s ----
    {
        const int wm = (warp & 1) * 32, wn = (warp >> 1) * 32;
#pragma unroll
        for (int mt = 0; mt < 2; mt++) {
            const int row0 = wm + mt * 16 + r;
            const int row1 = row0 + 8;
#pragma unroll
            for (int nt = 0; nt < 4; nt++) {
                const int col = wn + nt * 8 + cI * 2;
                if (row0 < WA_) {
                    float2 o = {cq[mt][nt][0], cq[mt][nt][1]};
                    *(float2*)&p_s[row0 * 132 + col] = o;
                }
                if (row1 < WA_) {
                    float2 o = {cq[mt][nt][2], cq[mt][nt][3]};
                    *(float2*)&p_s[row1 * 132 + col] = o;
                }
            }
        }
        // zero fp16 P pad rows (rows WA_..63, 68 words per row)
        for (int idx = tid; idx < (64 - WA_) * 68; idx += 256) {
            int row = WA_ + idx / 68, wrd = idx % 68;
            *(uint32_t*)(p_base + row * 528 + wrd * 4) = 0u;
        }

        // store V rows untransposed (2 x uint4 per thread)
        *(uint4*)&v_s[j * 40 + half16]     = vu0;
        *(uint4*)&v_s[j * 40 + half16 + 8] = vu1;
    }
    __syncthreads();

    // ---- softmax (fused scale+rpb, coalesced, depth-1 pipelined) ----
    const float scale = 0.17677669529663687f;
    const float* rpb_wh = rpb + (size_t)(w * H_ + h) * WA_ * KV_;
    {
        int i = warp;
        float r0 = 0.f, r1 = 0.f, r2 = 0.f, r3 = 0.f;
        if (i < WA_) {
            const float* rrow = rpb_wh + i * KV_;
            r0 = rrow[lane]; r1 = rrow[lane + 32];
            r2 = rrow[lane + 64]; r3 = rrow[lane + 96];
        }
        while (i < WA_) {
            const int inext = i + 8;
            float n0, n1, n2, n3;
            if (inext < WA_) {
                const float* rrow = rpb_wh + inext * KV_;
                n0 = rrow[lane]; n1 = rrow[lane + 32];
                n2 = rrow[lane + 64]; n3 = rrow[lane + 96];
            }
            float x0 = fmaf(p_s[i * 132 + lane],      scale, r0);
            float x1 = fmaf(p_s[i * 132 + lane + 32], scale, r1);
            float x2 = fmaf(p_s[i * 132 + lane + 64], scale, r2);
            float x3 = fmaf(p_s[i * 132 + lane + 96], scale, r3);
            float m = fmaxf(fmaxf(x0, x1), fmaxf(x2, x3));
#pragma unroll
            for (int off = 16; off; off >>= 1) m = fmaxf(m, __shfl_xor_sync(0xffffffffu, m, off));
            float e0 = __expf(x0 - m), e1 = __expf(x1 - m);
            float e2 = __expf(x2 - m), e3 = __expf(x3 - m);
            float s = e0 + e1 + e2 + e3;
#pragma unroll
            for (int off = 16; off; off >>= 1) s += __shfl_xor_sync(0xffffffffu, s, off);
            __half* ph = (__half*)(p_base + i * 528);
            ph[lane]      = __float2half(e0);
            ph[lane + 32] = __float2half(e1);
            ph[lane + 64] = __float2half(e2);
            ph[lane + 96] = __float2half(e3);
            if (lane == 0) inv_s[i] = 1.f / s;
            if (inext < WA_) { r0 = n0; r1 = n1; r2 = n2; r3 = n3; }
            i = inext;
        }
    }
    __syncthreads();

    // ---- PV: M=64 N=32 K=128 fp16; B via ldmatrix.trans on V rows ----
    {
        const int wm = (warp >> 1) * 16, wn = (warp & 1) * 16;
        const int vg = lane >> 3, vi = lane & 7;
        float c[2][4];
#pragma unroll
        for (int nt = 0; nt < 2; nt++)
#pragma unroll
            for (int f = 0; f < 4; f++) c[nt][f] = 0.f;

#pragma unroll
        for (int k16 = 0; k16 < KV_; k16 += 16) {
            uint32_t a0, a1, a2, a3;
            {
                uint32_t ad = sh_addr(p_base + (wm + a_row) * 528 + (k16 + a_koff) * 2);
                LDSM_X4(a0, a1, a2, a3, ad);
            }
            uint32_t bfr[2][2];
            {
                // lane group g: tile (kh = g&1, nt = g>>1); row vi within tile
                uint32_t ad = sh_addr(&v_s[(k16 + (vg & 1) * 8 + vi) * 40 + wn + (vg >> 1) * 8]);
                LDSM_X4_T(bfr[0][0], bfr[0][1], bfr[1][0], bfr[1][1], ad);
            }
#pragma unroll
            for (int nt = 0; nt < 2; nt++)
                MMA_F16(c[nt][0], c[nt][1], c[nt][2], c[nt][3],
                        a0, a1, a2, a3, bfr[nt][0], bfr[nt][1]);
        }

        const int row0 = wm + r, row1 = wm + r + 8;
#pragma unroll
        for (int nt = 0; nt < 2; nt++) {
            const int col = wn + nt * 8 + cI * 2;
            if (row0 < WA_) {
                float inv = inv_s[row0];
                uint32_t o = h2bits(c[nt][0] * inv, c[nt][1] * inv);
                *(uint32_t*)&attn_out[(((size_t)(b * NQ_ + w) * WA_) + row0) * C_ + h * HD_ + col] = o;
            }
            if (row1 < WA_) {
                float inv = inv_s[row1];
                uint32_t o = h2bits(c[nt][2] * inv, c[nt][3] * inv);
                *(uint32_t*)&attn_out[(((size_t)(b * NQ_ + w) * WA_) + row1) * C_ + h * HD_ + col] = o;
            }
        }
    }
}

// ============================================================
// launch
// ============================================================
extern "C" void kernel_launch(void* const* d_in, const int* in_sizes, int n_in,
                              void* d_out, int out_size)
{
    const float* x0      = (const float*)d_in[0];
    const float* x1      = (const float*)d_in[1];
    const float* qkv_w   = (const float*)d_in[2];
    const float* qkv_b   = (const float*)d_in[3];
    const float* proj_w  = (const float*)d_in[4];
    const float* proj_b  = (const float*)d_in[5];
    const float* rpb0_w1 = (const float*)d_in[6];
    const float* rpb0_b1 = (const float*)d_in[7];
    const float* rpb0_w2 = (const float*)d_in[8];
    const float* rpb0_b2 = (const float*)d_in[9];
    const float* rpb1_w1 = (const float*)d_in[10];
    const float* rpb1_b1 = (const float*)d_in[11];
    const float* rpb1_w2 = (const float*)d_in[12];
    const float* rpb1_b2 = (const float*)d_in[13];
    const float* coords0 = (const float*)d_in[14];
    const float* coords1 = (const float*)d_in[15];
    const int*   idx0    = (const int*)d_in[16];
    const int*   idx1    = (const int*)d_in[17];
    float* out = (float*)d_out;

    __half *qkv0, *qkv1, *attn_out;
    float *rpb;
    cudaGetSymbolAddress((void**)&qkv0, g_qkv0);
    cudaGetSymbolAddress((void**)&qkv1, g_qkv1);
    cudaGetSymbolAddress((void**)&rpb, g_rpb);
    cudaGetSymbolAddress((void**)&attn_out, g_attn_out);

    cudaFuncSetAttribute(attn_mma, cudaFuncAttributeMaxDynamicSharedMemorySize, SMEM_ATTN);

    gemm_f16<float, __half><<<dim3(M0_ / 128, 384 / 128), 256>>>(x0, qkv_w, qkv_b, qkv0, M0_, 384, 128);
    gemm_f16<float, __half><<<dim3(M1_ / 128, 384 / 128), 256>>>(x1, qkv_w, qkv_b, qkv1, M1_, 384, 128);
    rpb_kernel<<<(NQ_ * WA_ * KV_ + 255) / 256, 256>>>(
        coords0, coords1,
        rpb0_w1, rpb0_b1, rpb0_w2, rpb0_b2,
        rpb1_w1, rpb1_b1, rpb1_w2, rpb1_b2, rpb);
    attn_mma<<<dim3(NQ_, B_, H_), 256, SMEM_ATTN>>>(idx0, idx1, rpb, qkv0, qkv1, attn_out);
    gemm_f16<__half, float><<<dim3(M0_ / 128, C_ / 128), 256>>>(attn_out, proj_w, proj_b, out, M0_, C_, 128);
}

// round 14
// speedup vs baseline: 1.2650x; 1.0208x over previous
#include <cuda_runtime.h>
#include <cuda_fp16.h>
#include <cstdint>
#include <cstring>

#define B_   32
#define RES_ 56
#define C_   128
#define H_   4
#define HD_  32
#define WS_  7
#define NW_  8
#define NQ_  64
#define WA_  49
#define TOPK_ 64
#define KV_  128
#define P_   3136
#define M0_  (B_*P_)
#define M1_  (B_*NQ_)

__device__ __half g_qkv0[(size_t)M0_ * 384];
__device__ __half g_qkv1[(size_t)M1_ * 384];
__device__ float  g_rpb[(size_t)NQ_ * H_ * WA_ * KV_];
__device__ __half g_attn_out[(size_t)M0_ * C_];
__device__ __half g_x0h[(size_t)M0_ * C_];            // 25.7 MB
__device__ __half g_x1h[(size_t)M1_ * C_];
__device__ __half g_wqkv[384 * 128];
__device__ __half g_wproj[128 * 128];

#define MMA_F16(C0,C1,C2,C3,A0,A1,A2,A3,B0,B1) \
    asm volatile("mma.sync.aligned.m16n8k16.row.col.f32.f16.f16.f32 " \
        "{%0,%1,%2,%3},{%4,%5,%6,%7},{%8,%9},{%0,%1,%2,%3};" \
        : "+f"(C0), "+f"(C1), "+f"(C2), "+f"(C3) \
        : "r"(A0), "r"(A1), "r"(A2), "r"(A3), "r"(B0), "r"(B1))

#define LDSM_X4(R0,R1,R2,R3,ADDR) \
    asm volatile("ldmatrix.sync.aligned.m8n8.x4.shared.b16 {%0,%1,%2,%3}, [%4];" \
        : "=r"(R0), "=r"(R1), "=r"(R2), "=r"(R3) : "r"(ADDR))

#define LDSM_X4_T(R0,R1,R2,R3,ADDR) \
    asm volatile("ldmatrix.sync.aligned.m8n8.x4.trans.shared.b16 {%0,%1,%2,%3}, [%4];" \
        : "=r"(R0), "=r"(R1), "=r"(R2), "=r"(R3) : "r"(ADDR))

#define CP16(DST, SRC) \
    asm volatile("cp.async.cg.shared.global [%0], [%1], 16;" :: "r"(DST), "l"(SRC))
#define CP_COMMIT() asm volatile("cp.async.commit_group;")
#define CP_WAIT1()  asm volatile("cp.async.wait_group 1;")
#define CP_WAIT0()  asm volatile("cp.async.wait_group 0;")

__device__ __forceinline__ uint32_t sh_addr(const void* p) {
    return (uint32_t)__cvta_generic_to_shared(p);
}
__device__ __forceinline__ uint32_t h2bits(float a, float b) {
    __half2 h = __floats2half2_rn(a, b);
    return *(uint32_t*)&h;
}

// ============================================================
// fp32 -> fp16 conversion (grid-stride, float4 vectorized)
// ============================================================
__global__ void cvt_f2h(const float* __restrict__ src, __half* __restrict__ dst, int n4)
{
    int i = blockIdx.x * blockDim.x + threadIdx.x;
    for (; i < n4; i += gridDim.x * blockDim.x) {
        float4 v = ((const float4*)src)[i];
        __half2 h0 = __floats2half2_rn(v.x, v.y);
        __half2 h1 = __floats2half2_rn(v.z, v.w);
        uint2 u = {*(uint32_t*)&h0, *(uint32_t*)&h1};
        ((uint2*)dst)[i] = u;
    }
}

// ============================================================
// all-fp16 GEMM with cp.async 2-stage pipeline:
// C[M,N] = A[M,K]*B[N,K]^T + bias[N]; K multiple of 32.
// ============================================================
template <typename TO>
__global__ __launch_bounds__(256) void gemm_h16(
    const __half* __restrict__ A, const __half* __restrict__ Bm,
    const float* __restrict__ bias, TO* __restrict__ C,
    int M, int N, int K)
{
    __shared__ __half As[2][128 * 40];
    __shared__ __half Bs[2][128 * 40];

    const int tid = threadIdx.x;
    const int m0 = blockIdx.x * 128;
    const int n0 = blockIdx.y * 128;
    const int warp = tid >> 5, lane = tid & 31;
    const int wm = (warp >> 2) * 64;
    const int wn = (warp & 3) * 32;
    const int r = lane >> 2;
    const int cI = lane & 3;

    const int a_row  = lane & 15;
    const int a_koff = (lane >> 4) * 8;
    const int b_row  = (lane & 7) + (lane >> 4) * 8;
    const int b_koff = ((lane >> 3) & 1) * 8;

    float c[4][4][4];
#pragma unroll
    for (int mt = 0; mt < 4; mt++)
#pragma unroll
        for (int nt = 0; nt < 4; nt++)
#pragma unroll
            for (int f = 0; f < 4; f++) c[mt][nt][f] = 0.f;

    const int lr = tid >> 1;
    const int ls = (tid & 1) * 16;
    const __half* Arow = A  + (size_t)(m0 + lr) * K + ls;
    const __half* Brow = Bm + (size_t)(n0 + lr) * K + ls;
    const uint32_t sa = sh_addr(&As[0][lr * 40 + ls]);
    const uint32_t sb = sh_addr(&Bs[0][lr * 40 + ls]);
    const uint32_t stageBytes = 128 * 40 * 2;

    const int NK = K >> 5;

    // prefetch stage 0
    CP16(sa,      Arow);
    CP16(sa + 16, Arow + 8);
    CP16(sb,      Brow);
    CP16(sb + 16, Brow + 8);
    CP_COMMIT();

    for (int it = 0; it < NK; it++) {
        const int cur = it & 1;
        if (it + 1 < NK) {
            const int nxt = (it + 1) & 1;
            const int ko = (it + 1) << 5;
            CP16(sa + nxt * stageBytes,      Arow + ko);
            CP16(sa + nxt * stageBytes + 16, Arow + ko + 8);
            CP16(sb + nxt * stageBytes,      Brow + ko);
            CP16(sb + nxt * stageBytes + 16, Brow + ko + 8);
            CP_COMMIT();
            CP_WAIT1();
        } else {
            CP_WAIT0();
        }
        __syncthreads();

#pragma unroll
        for (int k16 = 0; k16 < 32; k16 += 16) {
            uint32_t a[4][4], b[4][2];
#pragma unroll
            for (int mt = 0; mt < 4; mt++) {
                uint32_t ad = sh_addr(&As[cur][(wm + mt * 16 + a_row) * 40 + k16 + a_koff]);
                LDSM_X4(a[mt][0], a[mt][1], a[mt][2], a[mt][3], ad);
            }
#pragma unroll
            for (int np = 0; np < 2; np++) {
                uint32_t ad = sh_addr(&Bs[cur][(wn + np * 16 + b_row) * 40 + k16 + b_koff]);
                LDSM_X4(b[2 * np][0], b[2 * np][1], b[2 * np + 1][0], b[2 * np + 1][1], ad);
            }
#pragma unroll
            for (int mt = 0; mt < 4; mt++)
#pragma unroll
                for (int nt = 0; nt < 4; nt++)
                    MMA_F16(c[mt][nt][0], c[mt][nt][1], c[mt][nt][2], c[mt][nt][3],
                            a[mt][0], a[mt][1], a[mt][2], a[mt][3],
                            b[nt][0], b[nt][1]);
        }
        __syncthreads();
    }

#pragma unroll
    for (int mt = 0; mt < 4; mt++) {
        const int row = m0 + wm + mt * 16 + r;
#pragma unroll
        for (int nt = 0; nt < 4; nt++) {
            const int col = n0 + wn + nt * 8 + cI * 2;
            float2 bb = *(const float2*)&bias[col];
            if constexpr (sizeof(TO) == 4) {
                float2 o0 = {c[mt][nt][0] + bb.x, c[mt][nt][1] + bb.y};
                float2 o1 = {c[mt][nt][2] + bb.x, c[mt][nt][3] + bb.y};
                *(float2*)&((float*)C)[(size_t)row * N + col]       = o0;
                *(float2*)&((float*)C)[(size_t)(row + 8) * N + col] = o1;
            } else {
                uint32_t o0 = h2bits(c[mt][nt][0] + bb.x, c[mt][nt][1] + bb.y);
                uint32_t o1 = h2bits(c[mt][nt][2] + bb.x, c[mt][nt][3] + bb.y);
                *(uint32_t*)&((__half*)C)[(size_t)row * N + col]       = o0;
                *(uint32_t*)&((__half*)C)[(size_t)(row + 8) * N + col] = o1;
            }
        }
    }
}

// ============================================================
// RPB MLP precompute (fp32 table)
// ============================================================
__global__ void rpb_kernel(
    const float* __restrict__ coords0, const float* __restrict__ coords1,
    const float* __restrict__ w1a, const float* __restrict__ b1a,
    const float* __restrict__ w2a, const float* __restrict__ b2a,
    const float* __restrict__ w1b, const float* __restrict__ b1b,
    const float* __restrict__ w2b, const float* __restrict__ b2b,
    float* __restrict__ rpb)
{
    int t = blockIdx.x * blockDim.x + threadIdx.x;
    const int TOT = NQ_ * WA_ * KV_;
    if (t >= TOT) return;
    int j = t & 127;
    int i = (t >> 7) % WA_;
    int w = t / (KV_ * WA_);

    const float *co, *w1, *b1, *w2, *b2;
    int jj;
    if (j < TOPK_) { co = coords0; jj = j;          w1 = w1a; b1 = b1a; w2 = w2a; b2 = b2a; }
    else           { co = coords1; jj = j - TOPK_;  w1 = w1b; b1 = b1b; w2 = w2b; b2 = b2b; }

    size_t cbase = ((size_t)(w * WA_ + i) * TOPK_ + jj) * 2;
    float cy = co[cbase + 0];
    float cx = co[cbase + 1];

    float o0 = b2[0], o1 = b2[1], o2 = b2[2], o3 = b2[3];
#pragma unroll
    for (int tt = 0; tt < HD_; tt++) {
        float hsum = fmaxf(fmaf(w1[tt * 2], cy, fmaf(w1[tt * 2 + 1], cx, b1[tt])), 0.f);
        o0 = fmaf(w2[0 * HD_ + tt], hsum, o0);
        o1 = fmaf(w2[1 * HD_ + tt], hsum, o1);
        o2 = fmaf(w2[2 * HD_ + tt], hsum, o2);
        o3 = fmaf(w2[3 * HD_ + tt], hsum, o3);
    }
    size_t base = ((size_t)(w * H_) * WA_ + i) * KV_ + j;
    const size_t hstride = (size_t)WA_ * KV_;
    rpb[base + 0 * hstride] = o0;
    rpb[base + 1 * hstride] = o1;
    rpb[base + 2 * hstride] = o2;
    rpb[base + 3 * hstride] = o3;
}

// ============================================================
// FP16 tensor-core attention (44288 B smem, 5 CTAs/SM) — R13 version
// ============================================================
#define SMEM_ATTN 44288

__global__ __launch_bounds__(256, 5) void attn_mma(
    const int* __restrict__ idx0, const int* __restrict__ idx1,
    const float* __restrict__ rpb,
    const __half* __restrict__ qkv0, const __half* __restrict__ qkv1,
    __half* __restrict__ attn_out)
{
    extern __shared__ char smem_raw[];
    __half* k_s  = (__half*)(smem_raw);
    __half* v_s  = (__half*)(smem_raw);
    float*  p_s  = (float*) (smem_raw + 10240);
    __half* q_s  = (__half*)(smem_raw + 10240);
    float*  inv_s= (float*) (smem_raw + 44032);
    char*   p_base = smem_raw + 10240;

    const int w = blockIdx.x, b = blockIdx.y, h = blockIdx.z;
    const int tid = threadIdx.x;
    const int warp = tid >> 5, lane = tid & 31;
    const int r = lane >> 2, cI = lane & 3;

    const int a_row  = lane & 15;
    const int a_koff = (lane >> 4) * 8;
    const int b_row  = (lane & 7) + (lane >> 4) * 8;
    const int b_koff = ((lane >> 3) & 1) * 8;

    const int j = tid >> 1;
    const int half16 = (tid & 1) * 16;
    const __half* basep;
    if (j < TOPK_) basep = qkv0 + ((size_t)b * P_ + idx0[w * TOPK_ + j]) * 384;
    else           basep = qkv1 + ((size_t)b * NQ_ + idx1[w * TOPK_ + (j - TOPK_)]) * 384;

    {
        const uint4* kp = (const uint4*)(basep + C_ + h * HD_ + half16);
        uint4 k0 = kp[0], k1 = kp[1];
        *(uint4*)&k_s[j * 40 + half16]     = k0;
        *(uint4*)&k_s[j * 40 + half16 + 8] = k1;
    }

    const int wy = w >> 3, wx = w & 7;
    {
        int i = tid >> 2, d = (tid & 3) * 8;
        uint4 val = {0u, 0u, 0u, 0u};
        if (i < WA_) {
            int pos = (wy * WS_ + i / WS_) * RES_ + wx * WS_ + i % WS_;
            val = *(const uint4*)(qkv0 + ((size_t)b * P_ + pos) * 384 + h * HD_ + d);
        }
        *(uint4*)&q_s[i * 40 + d] = val;
    }
    __syncthreads();

    float cq[2][4][4];
    {
        const int wm = (warp & 1) * 32, wn = (warp >> 1) * 32;
#pragma unroll
        for (int mt = 0; mt < 2; mt++)
#pragma unroll
            for (int nt = 0; nt < 4; nt++)
#pragma unroll
                for (int f = 0; f < 4; f++) cq[mt][nt][f] = 0.f;

#pragma unroll
        for (int k16 = 0; k16 < 32; k16 += 16) {
            uint32_t a[2][4], bb[4][2];
#pragma unroll
            for (int mt = 0; mt < 2; mt++) {
                uint32_t ad = sh_addr(&q_s[(wm + mt * 16 + a_row) * 40 + k16 + a_koff]);
                LDSM_X4(a[mt][0], a[mt][1], a[mt][2], a[mt][3], ad);
            }
#pragma unroll
            for (int np = 0; np < 2; np++) {
                uint32_t ad = sh_addr(&k_s[(wn + np * 16 + b_row) * 40 + k16 + b_koff]);
                LDSM_X4(bb[2 * np][0], bb[2 * np][1], bb[2 * np + 1][0], bb[2 * np + 1][1], ad);
            }
#pragma unroll
            for (int mt = 0; mt < 2; mt++)
#pragma unroll
                for (int nt = 0; nt < 4; nt++)
                    MMA_F16(cq[mt][nt][0], cq[mt][nt][1], cq[mt][nt][2], cq[mt][nt][3],
                            a[mt][0], a[mt][1], a[mt][2], a[mt][3],
                            bb[nt][0], bb[nt][1]);
        }
    }

    uint4 vu0, vu1;
    {
        const uint4* vp = (const uint4*)(basep + 2 * C_ + h * HD_ + half16);
        vu0 = vp[0]; vu1 = vp[1];
    }
    __syncthreads();

    {
        const int wm = (warp & 1) * 32, wn = (warp >> 1) * 32;
#pragma unroll
        for (int mt = 0; mt < 2; mt++) {
            const int row0 = wm + mt * 16 + r;
            const int row1 = row0 + 8;
#pragma unroll
            for (int nt = 0; nt < 4; nt++) {
                const int col = wn + nt * 8 + cI * 2;
                if (row0 < WA_) {
                    float2 o = {cq[mt][nt][0], cq[mt][nt][1]};
                    *(float2*)&p_s[row0 * 132 + col] = o;
                }
                if (row1 < WA_) {
                    float2 o = {cq[mt][nt][2], cq[mt][nt][3]};
                    *(float2*)&p_s[row1 * 132 + col] = o;
                }
            }
        }
        for (int idx = tid; idx < (64 - WA_) * 68; idx += 256) {
            int row = WA_ + idx / 68, wrd = idx % 68;
            *(uint32_t*)(p_base + row * 528 + wrd * 4) = 0u;
        }

        *(uint4*)&v_s[j * 40 + half16]     = vu0;
        *(uint4*)&v_s[j * 40 + half16 + 8] = vu1;
    }
    __syncthreads();

    const float scale = 0.17677669529663687f;
    const float* rpb_wh = rpb + (size_t)(w * H_ + h) * WA_ * KV_;
    {
        int i = warp;
        float r0 = 0.f, r1 = 0.f, r2 = 0.f, r3 = 0.f;
        if (i < WA_) {
            const float* rrow = rpb_wh + i * KV_;
            r0 = rrow[lane]; r1 = rrow[lane + 32];
            r2 = rrow[lane + 64]; r3 = rrow[lane + 96];
        }
        while (i < WA_) {
            const int inext = i + 8;
            float n0, n1, n2, n3;
            if (inext < WA_) {
                const float* rrow = rpb_wh + inext * KV_;
                n0 = rrow[lane]; n1 = rrow[lane + 32];
                n2 = rrow[lane + 64]; n3 = rrow[lane + 96];
            }
            float x0 = fmaf(p_s[i * 132 + lane],      scale, r0);
            float x1 = fmaf(p_s[i * 132 + lane + 32], scale, r1);
            float x2 = fmaf(p_s[i * 132 + lane + 64], scale, r2);
            float x3 = fmaf(p_s[i * 132 + lane + 96], scale, r3);
            float m = fmaxf(fmaxf(x0, x1), fmaxf(x2, x3));
#pragma unroll
            for (int off = 16; off; off >>= 1) m = fmaxf(m, __shfl_xor_sync(0xffffffffu, m, off));
            float e0 = __expf(x0 - m), e1 = __expf(x1 - m);
            float e2 = __expf(x2 - m), e3 = __expf(x3 - m);
            float s = e0 + e1 + e2 + e3;
#pragma unroll
            for (int off = 16; off; off >>= 1) s += __shfl_xor_sync(0xffffffffu, s, off);
            __half* ph = (__half*)(p_base + i * 528);
            ph[lane]      = __float2half(e0);
            ph[lane + 32] = __float2half(e1);
            ph[lane + 64] = __float2half(e2);
            ph[lane + 96] = __float2half(e3);
            if (lane == 0) inv_s[i] = 1.f / s;
            if (inext < WA_) { r0 = n0; r1 = n1; r2 = n2; r3 = n3; }
            i = inext;
        }
    }
    __syncthreads();

    {
        const int wm = (warp >> 1) * 16, wn = (warp & 1) * 16;
        const int vg = lane >> 3, vi = lane & 7;
        float c[2][4];
#pragma unroll
        for (int nt = 0; nt < 2; nt++)
#pragma unroll
            for (int f = 0; f < 4; f++) c[nt][f] = 0.f;

#pragma unroll
        for (int k16 = 0; k16 < KV_; k16 += 16) {
            uint32_t a0, a1, a2, a3;
            {
                uint32_t ad = sh_addr(p_base + (wm + a_row) * 528 + (k16 + a_koff) * 2);
                LDSM_X4(a0, a1, a2, a3, ad);
            }
            uint32_t bfr[2][2];
            {
                uint32_t ad = sh_addr(&v_s[(k16 + (vg & 1) * 8 + vi) * 40 + wn + (vg >> 1) * 8]);
                LDSM_X4_T(bfr[0][0], bfr[0][1], bfr[1][0], bfr[1][1], ad);
            }
#pragma unroll
            for (int nt = 0; nt < 2; nt++)
                MMA_F16(c[nt][0], c[nt][1], c[nt][2], c[nt][3],
                        a0, a1, a2, a3, bfr[nt][0], bfr[nt][1]);
        }

        const int row0 = wm + r, row1 = wm + r + 8;
#pragma unroll
        for (int nt = 0; nt < 2; nt++) {
            const int col = wn + nt * 8 + cI * 2;
            if (row0 < WA_) {
                float inv = inv_s[row0];
                uint32_t o = h2bits(c[nt][0] * inv, c[nt][1] * inv);
                *(uint32_t*)&attn_out[(((size_t)(b * NQ_ + w) * WA_) + row0) * C_ + h * HD_ + col] = o;
            }
            if (row1 < WA_) {
                float inv = inv_s[row1];
                uint32_t o = h2bits(c[nt][2] * inv, c[nt][3] * inv);
                *(uint32_t*)&attn_out[(((size_t)(b * NQ_ + w) * WA_) + row1) * C_ + h * HD_ + col] = o;
            }
        }
    }
}

// ============================================================
// launch
// ============================================================
extern "C" void kernel_launch(void* const* d_in, const int* in_sizes, int n_in,
                              void* d_out, int out_size)
{
    const float* x0      = (const float*)d_in[0];
    const float* x1      = (const float*)d_in[1];
    const float* qkv_w   = (const float*)d_in[2];
    const float* qkv_b   = (const float*)d_in[3];
    const float* proj_w  = (const float*)d_in[4];
    const float* proj_b  = (const float*)d_in[5];
    const float* rpb0_w1 = (const float*)d_in[6];
    const float* rpb0_b1 = (const float*)d_in[7];
    const float* rpb0_w2 = (const float*)d_in[8];
    const float* rpb0_b2 = (const float*)d_in[9];
    const float* rpb1_w1 = (const float*)d_in[10];
    const float* rpb1_b1 = (const float*)d_in[11];
    const float* rpb1_w2 = (const float*)d_in[12];
    const float* rpb1_b2 = (const float*)d_in[13];
    const float* coords0 = (const float*)d_in[14];
    const float* coords1 = (const float*)d_in[15];
    const int*   idx0    = (const int*)d_in[16];
    const int*   idx1    = (const int*)d_in[17];
    float* out = (float*)d_out;

    __half *qkv0, *qkv1, *attn_out, *x0h, *x1h, *wqkv, *wproj;
    float *rpb;
    cudaGetSymbolAddress((void**)&qkv0, g_qkv0);
    cudaGetSymbolAddress((void**)&qkv1, g_qkv1);
    cudaGetSymbolAddress((void**)&rpb, g_rpb);
    cudaGetSymbolAddress((void**)&attn_out, g_attn_out);
    cudaGetSymbolAddress((void**)&x0h, g_x0h);
    cudaGetSymbolAddress((void**)&x1h, g_x1h);
    cudaGetSymbolAddress((void**)&wqkv, g_wqkv);
    cudaGetSymbolAddress((void**)&wproj, g_wproj);

    cudaFuncSetAttribute(attn_mma, cudaFuncAttributeMaxDynamicSharedMemorySize, SMEM_ATTN);

    // fp32 -> fp16 conversions
    cvt_f2h<<<592, 256>>>(x0, x0h, (int)((size_t)M0_ * C_ / 4));
    cvt_f2h<<<64, 256>>>(x1, x1h, M1_ * C_ / 4);
    cvt_f2h<<<48, 256>>>(qkv_w, wqkv, 384 * 128 / 4);
    cvt_f2h<<<16, 256>>>(proj_w, wproj, 128 * 128 / 4);

    gemm_h16<__half><<<dim3(M0_ / 128, 384 / 128), 256>>>(x0h, wqkv, qkv_b, qkv0, M0_, 384, 128);
    gemm_h16<__half><<<dim3(M1_ / 128, 384 / 128), 256>>>(x1h, wqkv, qkv_b, qkv1, M1_, 384, 128);
    rpb_kernel<<<(NQ_ * WA_ * KV_ + 255) / 256, 256>>>(
        coords0, coords1,
        rpb0_w1, rpb0_b1, rpb0_w2, rpb0_b2,
        rpb1_w1, rpb1_b1, rpb1_w2, rpb1_b2, rpb);
    attn_mma<<<dim3(NQ_, B_, H_), 256, SMEM_ATTN>>>(idx0, idx1, rpb, qkv0, qkv1, attn_out);
    gemm_h16<float><<<dim3(M0_ / 128, C_ / 128), 256>>>(attn_out, wproj, proj_b, out, M0_, C_, 128);
}

// round 15
// speedup vs baseline: 1.3180x; 1.0419x over previous
#include <cuda_runtime.h>
#include <cuda_fp16.h>
#include <cstdint>
#include <cstring>

#define B_   32
#define RES_ 56
#define C_   128
#define H_   4
#define HD_  32
#define WS_  7
#define NW_  8
#define NQ_  64
#define WA_  49
#define TOPK_ 64
#define KV_  128
#define P_   3136
#define M0_  (B_*P_)
#define M1_  (B_*NQ_)

__device__ __half g_qkv0[(size_t)M0_ * 384];
__device__ __half g_qkv1[(size_t)M1_ * 384];
__device__ float  g_rpb[(size_t)NQ_ * H_ * WA_ * KV_];
__device__ __half g_attn_out[(size_t)M0_ * C_];
__device__ __half g_x0h[(size_t)M0_ * C_];
__device__ __half g_x1h[(size_t)M1_ * C_];
__device__ __half g_wqkv[384 * 128];
__device__ __half g_wproj[128 * 128];

#define MMA_F16(C0,C1,C2,C3,A0,A1,A2,A3,B0,B1) \
    asm volatile("mma.sync.aligned.m16n8k16.row.col.f32.f16.f16.f32 " \
        "{%0,%1,%2,%3},{%4,%5,%6,%7},{%8,%9},{%0,%1,%2,%3};" \
        : "+f"(C0), "+f"(C1), "+f"(C2), "+f"(C3) \
        : "r"(A0), "r"(A1), "r"(A2), "r"(A3), "r"(B0), "r"(B1))

#define LDSM_X4(R0,R1,R2,R3,ADDR) \
    asm volatile("ldmatrix.sync.aligned.m8n8.x4.shared.b16 {%0,%1,%2,%3}, [%4];" \
        : "=r"(R0), "=r"(R1), "=r"(R2), "=r"(R3) : "r"(ADDR))

#define LDSM_X4_T(R0,R1,R2,R3,ADDR) \
    asm volatile("ldmatrix.sync.aligned.m8n8.x4.trans.shared.b16 {%0,%1,%2,%3}, [%4];" \
        : "=r"(R0), "=r"(R1), "=r"(R2), "=r"(R3) : "r"(ADDR))

#define CP16(DST, SRC) \
    asm volatile("cp.async.cg.shared.global [%0], [%1], 16;" :: "r"(DST), "l"(SRC))
#define CP_COMMIT() asm volatile("cp.async.commit_group;")
#define CP_WAIT1()  asm volatile("cp.async.wait_group 1;")
#define CP_WAIT0()  asm volatile("cp.async.wait_group 0;")

__device__ __forceinline__ uint32_t sh_addr(const void* p) {
    return (uint32_t)__cvta_generic_to_shared(p);
}
__device__ __forceinline__ uint32_t h2bits(float a, float b) {
    __half2 h = __floats2half2_rn(a, b);
    return *(uint32_t*)&h;
}

// ============================================================
// fp32 -> fp16 conversion (grid-stride, float4 vectorized)
// ============================================================
__global__ void cvt_f2h(const float* __restrict__ src, __half* __restrict__ dst, int n4)
{
    int i = blockIdx.x * blockDim.x + threadIdx.x;
    for (; i < n4; i += gridDim.x * blockDim.x) {
        float4 v = ((const float4*)src)[i];
        __half2 h0 = __floats2half2_rn(v.x, v.y);
        __half2 h1 = __floats2half2_rn(v.z, v.w);
        uint2 u = {*(uint32_t*)&h0, *(uint32_t*)&h1};
        ((uint2*)dst)[i] = u;
    }
}

// ============================================================
// all-fp16 GEMM with cp.async 2-stage pipeline:
// C[M,N] = A[M,K]*B[N,K]^T + bias[N]; K multiple of 32.
// fp16 output staged through smem for coalesced 16B stores.
// ============================================================
template <typename TO>
__global__ __launch_bounds__(256) void gemm_h16(
    const __half* __restrict__ A, const __half* __restrict__ Bm,
    const float* __restrict__ bias, TO* __restrict__ C,
    int M, int N, int K)
{
    __shared__ __half As[2][128 * 40];
    __shared__ __half Bs[2][128 * 40];   // As+Bs (40960 B) reused as C-stage (34816 B)

    const int tid = threadIdx.x;
    const int m0 = blockIdx.x * 128;
    const int n0 = blockIdx.y * 128;
    const int warp = tid >> 5, lane = tid & 31;
    const int wm = (warp >> 2) * 64;
    const int wn = (warp & 3) * 32;
    const int r = lane >> 2;
    const int cI = lane & 3;

    const int a_row  = lane & 15;
    const int a_koff = (lane >> 4) * 8;
    const int b_row  = (lane & 7) + (lane >> 4) * 8;
    const int b_koff = ((lane >> 3) & 1) * 8;

    float c[4][4][4];
#pragma unroll
    for (int mt = 0; mt < 4; mt++)
#pragma unroll
        for (int nt = 0; nt < 4; nt++)
#pragma unroll
            for (int f = 0; f < 4; f++) c[mt][nt][f] = 0.f;

    const int lr = tid >> 1;
    const int ls = (tid & 1) * 16;
    const __half* Arow = A  + (size_t)(m0 + lr) * K + ls;
    const __half* Brow = Bm + (size_t)(n0 + lr) * K + ls;
    const uint32_t sa = sh_addr(&As[0][lr * 40 + ls]);
    const uint32_t sb = sh_addr(&Bs[0][lr * 40 + ls]);
    const uint32_t stageBytes = 128 * 40 * 2;

    const int NK = K >> 5;

    CP16(sa,      Arow);
    CP16(sa + 16, Arow + 8);
    CP16(sb,      Brow);
    CP16(sb + 16, Brow + 8);
    CP_COMMIT();

    for (int it = 0; it < NK; it++) {
        const int cur = it & 1;
        if (it + 1 < NK) {
            const int nxt = (it + 1) & 1;
            const int ko = (it + 1) << 5;
            CP16(sa + nxt * stageBytes,      Arow + ko);
            CP16(sa + nxt * stageBytes + 16, Arow + ko + 8);
            CP16(sb + nxt * stageBytes,      Brow + ko);
            CP16(sb + nxt * stageBytes + 16, Brow + ko + 8);
            CP_COMMIT();
            CP_WAIT1();
        } else {
            CP_WAIT0();
        }
        __syncthreads();

#pragma unroll
        for (int k16 = 0; k16 < 32; k16 += 16) {
            uint32_t a[4][4], b[4][2];
#pragma unroll
            for (int mt = 0; mt < 4; mt++) {
                uint32_t ad = sh_addr(&As[cur][(wm + mt * 16 + a_row) * 40 + k16 + a_koff]);
                LDSM_X4(a[mt][0], a[mt][1], a[mt][2], a[mt][3], ad);
            }
#pragma unroll
            for (int np = 0; np < 2; np++) {
                uint32_t ad = sh_addr(&Bs[cur][(wn + np * 16 + b_row) * 40 + k16 + b_koff]);
                LDSM_X4(b[2 * np][0], b[2 * np][1], b[2 * np + 1][0], b[2 * np + 1][1], ad);
            }
#pragma unroll
            for (int mt = 0; mt < 4; mt++)
#pragma unroll
                for (int nt = 0; nt < 4; nt++)
                    MMA_F16(c[mt][nt][0], c[mt][nt][1], c[mt][nt][2], c[mt][nt][3],
                            a[mt][0], a[mt][1], a[mt][2], a[mt][3],
                            b[nt][0], b[nt][1]);
        }
        __syncthreads();
    }

    if constexpr (sizeof(TO) == 4) {
        // fp32 output: direct stores (4 lanes x 8B = full 32B sector)
#pragma unroll
        for (int mt = 0; mt < 4; mt++) {
            const int row = m0 + wm + mt * 16 + r;
#pragma unroll
            for (int nt = 0; nt < 4; nt++) {
                const int col = n0 + wn + nt * 8 + cI * 2;
                float2 bb = *(const float2*)&bias[col];
                float2 o0 = {c[mt][nt][0] + bb.x, c[mt][nt][1] + bb.y};
                float2 o1 = {c[mt][nt][2] + bb.x, c[mt][nt][3] + bb.y};
                *(float2*)&((float*)C)[(size_t)row * N + col]       = o0;
                *(float2*)&((float*)C)[(size_t)(row + 8) * N + col] = o1;
            }
        }
    } else {
        // fp16 output: stage tile in smem (stride 136 halves), then coalesced uint4 stores
        __half* Cs = (__half*)As;   // 128*136*2 = 34816 B <= 40960 B
#pragma unroll
        for (int mt = 0; mt < 4; mt++) {
            const int row = wm + mt * 16 + r;
#pragma unroll
            for (int nt = 0; nt < 4; nt++) {
                const int col = wn + nt * 8 + cI * 2;
                float2 bb = *(const float2*)&bias[n0 + col];
                *(uint32_t*)&Cs[row * 136 + col]       = h2bits(c[mt][nt][0] + bb.x, c[mt][nt][1] + bb.y);
                *(uint32_t*)&Cs[(row + 8) * 136 + col] = h2bits(c[mt][nt][2] + bb.x, c[mt][nt][3] + bb.y);
            }
        }
        __syncthreads();
#pragma unroll
        for (int it2 = 0; it2 < 8; it2++) {
            const int idx = tid + it2 * 256;            // 2048 uint4 total
            const int row = idx >> 4, chunk = idx & 15; // 16 x 8-half chunks per row
            uint4 v = *(const uint4*)&Cs[row * 136 + chunk * 8];
            *(uint4*)&((__half*)C)[(size_t)(m0 + row) * N + n0 + chunk * 8] = v;
        }
    }
}

// ============================================================
// RPB MLP precompute (fp32 table)
// ============================================================
__global__ void rpb_kernel(
    const float* __restrict__ coords0, const float* __restrict__ coords1,
    const float* __restrict__ w1a, const float* __restrict__ b1a,
    const float* __restrict__ w2a, const float* __restrict__ b2a,
    const float* __restrict__ w1b, const float* __restrict__ b1b,
    const float* __restrict__ w2b, const float* __restrict__ b2b,
    float* __restrict__ rpb)
{
    int t = blockIdx.x * blockDim.x + threadIdx.x;
    const int TOT = NQ_ * WA_ * KV_;
    if (t >= TOT) return;
    int j = t & 127;
    int i = (t >> 7) % WA_;
    int w = t / (KV_ * WA_);

    const float *co, *w1, *b1, *w2, *b2;
    int jj;
    if (j < TOPK_) { co = coords0; jj = j;          w1 = w1a; b1 = b1a; w2 = w2a; b2 = b2a; }
    else           { co = coords1; jj = j - TOPK_;  w1 = w1b; b1 = b1b; w2 = w2b; b2 = b2b; }

    size_t cbase = ((size_t)(w * WA_ + i) * TOPK_ + jj) * 2;
    float cy = co[cbase + 0];
    float cx = co[cbase + 1];

    float o0 = b2[0], o1 = b2[1], o2 = b2[2], o3 = b2[3];
#pragma unroll
    for (int tt = 0; tt < HD_; tt++) {
        float hsum = fmaxf(fmaf(w1[tt * 2], cy, fmaf(w1[tt * 2 + 1], cx, b1[tt])), 0.f);
        o0 = fmaf(w2[0 * HD_ + tt], hsum, o0);
        o1 = fmaf(w2[1 * HD_ + tt], hsum, o1);
        o2 = fmaf(w2[2 * HD_ + tt], hsum, o2);
        o3 = fmaf(w2[3 * HD_ + tt], hsum, o3);
    }
    size_t base = ((size_t)(w * H_) * WA_ + i) * KV_ + j;
    const size_t hstride = (size_t)WA_ * KV_;
    rpb[base + 0 * hstride] = o0;
    rpb[base + 1 * hstride] = o1;
    rpb[base + 2 * hstride] = o2;
    rpb[base + 3 * hstride] = o3;
}

// ============================================================
// FP16 tensor-core attention (44288 B smem, 5 CTAs/SM)
// ============================================================
#define SMEM_ATTN 44288

__global__ __launch_bounds__(256, 5) void attn_mma(
    const int* __restrict__ idx0, const int* __restrict__ idx1,
    const float* __restrict__ rpb,
    const __half* __restrict__ qkv0, const __half* __restrict__ qkv1,
    __half* __restrict__ attn_out)
{
    extern __shared__ char smem_raw[];
    __half* k_s  = (__half*)(smem_raw);
    __half* v_s  = (__half*)(smem_raw);
    float*  p_s  = (float*) (smem_raw + 10240);
    __half* q_s  = (__half*)(smem_raw + 10240);
    float*  inv_s= (float*) (smem_raw + 44032);
    char*   p_base = smem_raw + 10240;

    const int w = blockIdx.x, b = blockIdx.y, h = blockIdx.z;
    const int tid = threadIdx.x;
    const int warp = tid >> 5, lane = tid & 31;
    const int r = lane >> 2, cI = lane & 3;

    const int a_row  = lane & 15;
    const int a_koff = (lane >> 4) * 8;
    const int b_row  = (lane & 7) + (lane >> 4) * 8;
    const int b_koff = ((lane >> 3) & 1) * 8;

    const int j = tid >> 1;
    const int half16 = (tid & 1) * 16;
    const __half* basep;
    if (j < TOPK_) basep = qkv0 + ((size_t)b * P_ + idx0[w * TOPK_ + j]) * 384;
    else           basep = qkv1 + ((size_t)b * NQ_ + idx1[w * TOPK_ + (j - TOPK_)]) * 384;

    {
        const uint4* kp = (const uint4*)(basep + C_ + h * HD_ + half16);
        uint4 k0 = kp[0], k1 = kp[1];
        *(uint4*)&k_s[j * 40 + half16]     = k0;
        *(uint4*)&k_s[j * 40 + half16 + 8] = k1;
    }

    const int wy = w >> 3, wx = w & 7;
    {
        int i = tid >> 2, d = (tid & 3) * 8;
        uint4 val = {0u, 0u, 0u, 0u};
        if (i < WA_) {
            int pos = (wy * WS_ + i / WS_) * RES_ + wx * WS_ + i % WS_;
            val = *(const uint4*)(qkv0 + ((size_t)b * P_ + pos) * 384 + h * HD_ + d);
        }
        *(uint4*)&q_s[i * 40 + d] = val;
    }
    __syncthreads();

    float cq[2][4][4];
    {
        const int wm = (warp & 1) * 32, wn = (warp >> 1) * 32;
#pragma unroll
        for (int mt = 0; mt < 2; mt++)
#pragma unroll
            for (int nt = 0; nt < 4; nt++)
#pragma unroll
                for (int f = 0; f < 4; f++) cq[mt][nt][f] = 0.f;

#pragma unroll
        for (int k16 = 0; k16 < 32; k16 += 16) {
            uint32_t a[2][4], bb[4][2];
#pragma unroll
            for (int mt = 0; mt < 2; mt++) {
                uint32_t ad = sh_addr(&q_s[(wm + mt * 16 + a_row) * 40 + k16 + a_koff]);
                LDSM_X4(a[mt][0], a[mt][1], a[mt][2], a[mt][3], ad);
            }
#pragma unroll
            for (int np = 0; np < 2; np++) {
                uint32_t ad = sh_addr(&k_s[(wn + np * 16 + b_row) * 40 + k16 + b_koff]);
                LDSM_X4(bb[2 * np][0], bb[2 * np][1], bb[2 * np + 1][0], bb[2 * np + 1][1], ad);
            }
#pragma unroll
            for (int mt = 0; mt < 2; mt++)
#pragma unroll
                for (int nt = 0; nt < 4; nt++)
                    MMA_F16(cq[mt][nt][0], cq[mt][nt][1], cq[mt][nt][2], cq[mt][nt][3],
                            a[mt][0], a[mt][1], a[mt][2], a[mt][3],
                            bb[nt][0], bb[nt][1]);
        }
    }

    uint4 vu0, vu1;
    {
        const uint4* vp = (const uint4*)(basep + 2 * C_ + h * HD_ + half16);
        vu0 = vp[0]; vu1 = vp[1];
    }
    __syncthreads();

    {
        const int wm = (warp & 1) * 32, wn = (warp >> 1) * 32;
#pragma unroll
        for (int mt = 0; mt < 2; mt++) {
            const int row0 = wm + mt * 16 + r;
            const int row1 = row0 + 8;
#pragma unroll
            for (int nt = 0; nt < 4; nt++) {
                const int col = wn + nt * 8 + cI * 2;
                if (row0 < WA_) {
                    float2 o = {cq[mt][nt][0], cq[mt][nt][1]};
                    *(float2*)&p_s[row0 * 132 + col] = o;
                }
                if (row1 < WA_) {
                    float2 o = {cq[mt][nt][2], cq[mt][nt][3]};
                    *(float2*)&p_s[row1 * 132 + col] = o;
                }
            }
        }
        for (int idx = tid; idx < (64 - WA_) * 68; idx += 256) {
            int row = WA_ + idx / 68, wrd = idx % 68;
            *(uint32_t*)(p_base + row * 528 + wrd * 4) = 0u;
        }

        *(uint4*)&v_s[j * 40 + half16]     = vu0;
        *(uint4*)&v_s[j * 40 + half16 + 8] = vu1;
    }
    __syncthreads();

    const float scale = 0.17677669529663687f;
    const float* rpb_wh = rpb + (size_t)(w * H_ + h) * WA_ * KV_;
    {
        int i = warp;
        float r0 = 0.f, r1 = 0.f, r2 = 0.f, r3 = 0.f;
        if (i < WA_) {
            const float* rrow = rpb_wh + i * KV_;
            r0 = rrow[lane]; r1 = rrow[lane + 32];
            r2 = rrow[lane + 64]; r3 = rrow[lane + 96];
        }
        while (i < WA_) {
            const int inext = i + 8;
            float n0, n1, n2, n3;
            if (inext < WA_) {
                const float* rrow = rpb_wh + inext * KV_;
                n0 = rrow[lane]; n1 = rrow[lane + 32];
                n2 = rrow[lane + 64]; n3 = rrow[lane + 96];
            }
            float x0 = fmaf(p_s[i * 132 + lane],      scale, r0);
            float x1 = fmaf(p_s[i * 132 + lane + 32], scale, r1);
            float x2 = fmaf(p_s[i * 132 + lane + 64], scale, r2);
            float x3 = fmaf(p_s[i * 132 + lane + 96], scale, r3);
            float m = fmaxf(fmaxf(x0, x1), fmaxf(x2, x3));
#pragma unroll
            for (int off = 16; off; off >>= 1) m = fmaxf(m, __shfl_xor_sync(0xffffffffu, m, off));
            float e0 = __expf(x0 - m), e1 = __expf(x1 - m);
            float e2 = __expf(x2 - m), e3 = __expf(x3 - m);
            float s = e0 + e1 + e2 + e3;
#pragma unroll
            for (int off = 16; off; off >>= 1) s += __shfl_xor_sync(0xffffffffu, s, off);
            __half* ph = (__half*)(p_base + i * 528);
            ph[lane]      = __float2half(e0);
            ph[lane + 32] = __float2half(e1);
            ph[lane + 64] = __float2half(e2);
            ph[lane + 96] = __float2half(e3);
            if (lane == 0) inv_s[i] = 1.f / s;
            if (inext < WA_) { r0 = n0; r1 = n1; r2 = n2; r3 = n3; }
            i = inext;
        }
    }
    __syncthreads();

    {
        const int wm = (warp >> 1) * 16, wn = (warp & 1) * 16;
        const int vg = lane >> 3, vi = lane & 7;
        float c[2][4];
#pragma unroll
        for (int nt = 0; nt < 2; nt++)
#pragma unroll
            for (int f = 0; f < 4; f++) c[nt][f] = 0.f;

#pragma unroll
        for (int k16 = 0; k16 < KV_; k16 += 16) {
            uint32_t a0, a1, a2, a3;
            {
                uint32_t ad = sh_addr(p_base + (wm + a_row) * 528 + (k16 + a_koff) * 2);
                LDSM_X4(a0, a1, a2, a3, ad);
            }
            uint32_t bfr[2][2];
            {
                uint32_t ad = sh_addr(&v_s[(k16 + (vg & 1) * 8 + vi) * 40 + wn + (vg >> 1) * 8]);
                LDSM_X4_T(bfr[0][0], bfr[0][1], bfr[1][0], bfr[1][1], ad);
            }
#pragma unroll
            for (int nt = 0; nt < 2; nt++)
                MMA_F16(c[nt][0], c[nt][1], c[nt][2], c[nt][3],
                        a0, a1, a2, a3, bfr[nt][0], bfr[nt][1]);
        }

        const int row0 = wm + r, row1 = wm + r + 8;
#pragma unroll
        for (int nt = 0; nt < 2; nt++) {
            const int col = wn + nt * 8 + cI * 2;
            if (row0 < WA_) {
                float inv = inv_s[row0];
                uint32_t o = h2bits(c[nt][0] * inv, c[nt][1] * inv);
                *(uint32_t*)&attn_out[(((size_t)(b * NQ_ + w) * WA_) + row0) * C_ + h * HD_ + col] = o;
            }
            if (row1 < WA_) {
                float inv = inv_s[row1];
                uint32_t o = h2bits(c[nt][2] * inv, c[nt][3] * inv);
                *(uint32_t*)&attn_out[(((size_t)(b * NQ_ + w) * WA_) + row1) * C_ + h * HD_ + col] = o;
            }
        }
    }
}

// ============================================================
// launch
// ============================================================
extern "C" void kernel_launch(void* const* d_in, const int* in_sizes, int n_in,
                              void* d_out, int out_size)
{
    const float* x0      = (const float*)d_in[0];
    const float* x1      = (const float*)d_in[1];
    const float* qkv_w   = (const float*)d_in[2];
    const float* qkv_b   = (const float*)d_in[3];
    const float* proj_w  = (const float*)d_in[4];
    const float* proj_b  = (const float*)d_in[5];
    const float* rpb0_w1 = (const float*)d_in[6];
    const float* rpb0_b1 = (const float*)d_in[7];
    const float* rpb0_w2 = (const float*)d_in[8];
    const float* rpb0_b2 = (const float*)d_in[9];
    const float* rpb1_w1 = (const float*)d_in[10];
    const float* rpb1_b1 = (const float*)d_in[11];
    const float* rpb1_w2 = (const float*)d_in[12];
    const float* rpb1_b2 = (const float*)d_in[13];
    const float* coords0 = (const float*)d_in[14];
    const float* coords1 = (const float*)d_in[15];
    const int*   idx0    = (const int*)d_in[16];
    const int*   idx1    = (const int*)d_in[17];
    float* out = (float*)d_out;

    __half *qkv0, *qkv1, *attn_out, *x0h, *x1h, *wqkv, *wproj;
    float *rpb;
    cudaGetSymbolAddress((void**)&qkv0, g_qkv0);
    cudaGetSymbolAddress((void**)&qkv1, g_qkv1);
    cudaGetSymbolAddress((void**)&rpb, g_rpb);
    cudaGetSymbolAddress((void**)&attn_out, g_attn_out);
    cudaGetSymbolAddress((void**)&x0h, g_x0h);
    cudaGetSymbolAddress((void**)&x1h, g_x1h);
    cudaGetSymbolAddress((void**)&wqkv, g_wqkv);
    cudaGetSymbolAddress((void**)&wproj, g_wproj);

    cudaFuncSetAttribute(attn_mma, cudaFuncAttributeMaxDynamicSharedMemorySize, SMEM_ATTN);

    cvt_f2h<<<592, 256>>>(x0, x0h, (int)((size_t)M0_ * C_ / 4));
    cvt_f2h<<<64, 256>>>(x1, x1h, M1_ * C_ / 4);
    cvt_f2h<<<48, 256>>>(qkv_w, wqkv, 384 * 128 / 4);
    cvt_f2h<<<16, 256>>>(proj_w, wproj, 128 * 128 / 4);

    gemm_h16<__half><<<dim3(M0_ / 128, 384 / 128), 256>>>(x0h, wqkv, qkv_b, qkv0, M0_, 384, 128);
    gemm_h16<__half><<<dim3(M1_ / 128, 384 / 128), 256>>>(x1h, wqkv, qkv_b, qkv1, M1_, 384, 128);
    rpb_kernel<<<(NQ_ * WA_ * KV_ + 255) / 256, 256>>>(
        coords0, coords1,
        rpb0_w1, rpb0_b1, rpb0_w2, rpb0_b2,
        rpb1_w1, rpb1_b1, rpb1_w2, rpb1_b2, rpb);
    attn_mma<<<dim3(NQ_, B_, H_), 256, SMEM_ATTN>>>(idx0, idx1, rpb, qkv0, qkv1, attn_out);
    gemm_h16<float><<<dim3(M0_ / 128, C_ / 128), 256>>>(attn_out, wproj, proj_b, out, M0_, C_, 128);
}

// round 16
// speedup vs baseline: 1.3959x; 1.0591x over previous
#include <cuda_runtime.h>
#include <cuda_fp16.h>
#include <cstdint>
#include <cstring>

#define B_   32
#define RES_ 56
#define C_   128
#define H_   4
#define HD_  32
#define WS_  7
#define NW_  8
#define NQ_  64
#define WA_  49
#define TOPK_ 64
#define KV_  128
#define P_   3136
#define M0_  (B_*P_)
#define M1_  (B_*NQ_)

__device__ __half g_qkv0[(size_t)M0_ * 384];
__device__ __half g_qkv1[(size_t)M1_ * 384];
__device__ __half g_rpb[(size_t)NQ_ * H_ * WA_ * KV_];
__device__ __half g_attn_out[(size_t)M0_ * C_];
__device__ __half g_x0h[(size_t)M0_ * C_];
__device__ __half g_x1h[(size_t)M1_ * C_];
__device__ __half g_wqkv[384 * 128];
__device__ __half g_wproj[128 * 128];

#define MMA_F16(C0,C1,C2,C3,A0,A1,A2,A3,B0,B1) \
    asm volatile("mma.sync.aligned.m16n8k16.row.col.f32.f16.f16.f32 " \
        "{%0,%1,%2,%3},{%4,%5,%6,%7},{%8,%9},{%0,%1,%2,%3};" \
        : "+f"(C0), "+f"(C1), "+f"(C2), "+f"(C3) \
        : "r"(A0), "r"(A1), "r"(A2), "r"(A3), "r"(B0), "r"(B1))

#define LDSM_X4(R0,R1,R2,R3,ADDR) \
    asm volatile("ldmatrix.sync.aligned.m8n8.x4.shared.b16 {%0,%1,%2,%3}, [%4];" \
        : "=r"(R0), "=r"(R1), "=r"(R2), "=r"(R3) : "r"(ADDR))

#define LDSM_X4_T(R0,R1,R2,R3,ADDR) \
    asm volatile("ldmatrix.sync.aligned.m8n8.x4.trans.shared.b16 {%0,%1,%2,%3}, [%4];" \
        : "=r"(R0), "=r"(R1), "=r"(R2), "=r"(R3) : "r"(ADDR))

#define CP16(DST, SRC) \
    asm volatile("cp.async.cg.shared.global [%0], [%1], 16;" :: "r"(DST), "l"(SRC))
#define CP_COMMIT() asm volatile("cp.async.commit_group;")
#define CP_WAIT1()  asm volatile("cp.async.wait_group 1;")
#define CP_WAIT0()  asm volatile("cp.async.wait_group 0;")

__device__ __forceinline__ uint32_t sh_addr(const void* p) {
    return (uint32_t)__cvta_generic_to_shared(p);
}
__device__ __forceinline__ uint32_t h2bits(float a, float b) {
    __half2 h = __floats2half2_rn(a, b);
    return *(uint32_t*)&h;
}

// ============================================================
// fp32 -> fp16 conversion
// ============================================================
__global__ void cvt_f2h(const float* __restrict__ src, __half* __restrict__ dst, int n4)
{
    int i = blockIdx.x * blockDim.x + threadIdx.x;
    for (; i < n4; i += gridDim.x * blockDim.x) {
        float4 v = ((const float4*)src)[i];
        __half2 h0 = __floats2half2_rn(v.x, v.y);
        __half2 h1 = __floats2half2_rn(v.z, v.w);
        uint2 u = {*(uint32_t*)&h0, *(uint32_t*)&h1};
        ((uint2*)dst)[i] = u;
    }
}

// ============================================================
// all-fp16 GEMM with cp.async 2-stage pipeline (R15 version)
// ============================================================
template <typename TO>
__global__ __launch_bounds__(256) void gemm_h16(
    const __half* __restrict__ A, const __half* __restrict__ Bm,
    const float* __restrict__ bias, TO* __restrict__ C,
    int M, int N, int K)
{
    __shared__ __half As[2][128 * 40];
    __shared__ __half Bs[2][128 * 40];

    const int tid = threadIdx.x;
    const int m0 = blockIdx.x * 128;
    const int n0 = blockIdx.y * 128;
    const int warp = tid >> 5, lane = tid & 31;
    const int wm = (warp >> 2) * 64;
    const int wn = (warp & 3) * 32;
    const int r = lane >> 2;
    const int cI = lane & 3;

    const int a_row  = lane & 15;
    const int a_koff = (lane >> 4) * 8;
    const int b_row  = (lane & 7) + (lane >> 4) * 8;
    const int b_koff = ((lane >> 3) & 1) * 8;

    float c[4][4][4];
#pragma unroll
    for (int mt = 0; mt < 4; mt++)
#pragma unroll
        for (int nt = 0; nt < 4; nt++)
#pragma unroll
            for (int f = 0; f < 4; f++) c[mt][nt][f] = 0.f;

    const int lr = tid >> 1;
    const int ls = (tid & 1) * 16;
    const __half* Arow = A  + (size_t)(m0 + lr) * K + ls;
    const __half* Brow = Bm + (size_t)(n0 + lr) * K + ls;
    const uint32_t sa = sh_addr(&As[0][lr * 40 + ls]);
    const uint32_t sb = sh_addr(&Bs[0][lr * 40 + ls]);
    const uint32_t stageBytes = 128 * 40 * 2;

    const int NK = K >> 5;

    CP16(sa,      Arow);
    CP16(sa + 16, Arow + 8);
    CP16(sb,      Brow);
    CP16(sb + 16, Brow + 8);
    CP_COMMIT();

    for (int it = 0; it < NK; it++) {
        const int cur = it & 1;
        if (it + 1 < NK) {
            const int nxt = (it + 1) & 1;
            const int ko = (it + 1) << 5;
            CP16(sa + nxt * stageBytes,      Arow + ko);
            CP16(sa + nxt * stageBytes + 16, Arow + ko + 8);
            CP16(sb + nxt * stageBytes,      Brow + ko);
            CP16(sb + nxt * stageBytes + 16, Brow + ko + 8);
            CP_COMMIT();
            CP_WAIT1();
        } else {
            CP_WAIT0();
        }
        __syncthreads();

#pragma unroll
        for (int k16 = 0; k16 < 32; k16 += 16) {
            uint32_t a[4][4], b[4][2];
#pragma unroll
            for (int mt = 0; mt < 4; mt++) {
                uint32_t ad = sh_addr(&As[cur][(wm + mt * 16 + a_row) * 40 + k16 + a_koff]);
                LDSM_X4(a[mt][0], a[mt][1], a[mt][2], a[mt][3], ad);
            }
#pragma unroll
            for (int np = 0; np < 2; np++) {
                uint32_t ad = sh_addr(&Bs[cur][(wn + np * 16 + b_row) * 40 + k16 + b_koff]);
                LDSM_X4(b[2 * np][0], b[2 * np][1], b[2 * np + 1][0], b[2 * np + 1][1], ad);
            }
#pragma unroll
            for (int mt = 0; mt < 4; mt++)
#pragma unroll
                for (int nt = 0; nt < 4; nt++)
                    MMA_F16(c[mt][nt][0], c[mt][nt][1], c[mt][nt][2], c[mt][nt][3],
                            a[mt][0], a[mt][1], a[mt][2], a[mt][3],
                            b[nt][0], b[nt][1]);
        }
        __syncthreads();
    }

    if constexpr (sizeof(TO) == 4) {
#pragma unroll
        for (int mt = 0; mt < 4; mt++) {
            const int row = m0 + wm + mt * 16 + r;
#pragma unroll
            for (int nt = 0; nt < 4; nt++) {
                const int col = n0 + wn + nt * 8 + cI * 2;
                float2 bb = *(const float2*)&bias[col];
                float2 o0 = {c[mt][nt][0] + bb.x, c[mt][nt][1] + bb.y};
                float2 o1 = {c[mt][nt][2] + bb.x, c[mt][nt][3] + bb.y};
                *(float2*)&((float*)C)[(size_t)row * N + col]       = o0;
                *(float2*)&((float*)C)[(size_t)(row + 8) * N + col] = o1;
            }
        }
    } else {
        __half* Cs = (__half*)As;
#pragma unroll
        for (int mt = 0; mt < 4; mt++) {
            const int row = wm + mt * 16 + r;
#pragma unroll
            for (int nt = 0; nt < 4; nt++) {
                const int col = wn + nt * 8 + cI * 2;
                float2 bb = *(const float2*)&bias[n0 + col];
                *(uint32_t*)&Cs[row * 136 + col]       = h2bits(c[mt][nt][0] + bb.x, c[mt][nt][1] + bb.y);
                *(uint32_t*)&Cs[(row + 8) * 136 + col] = h2bits(c[mt][nt][2] + bb.x, c[mt][nt][3] + bb.y);
            }
        }
        __syncthreads();
#pragma unroll
        for (int it2 = 0; it2 < 8; it2++) {
            const int idx = tid + it2 * 256;
            const int row = idx >> 4, chunk = idx & 15;
            uint4 v = *(const uint4*)&Cs[row * 136 + chunk * 8];
            *(uint4*)&((__half*)C)[(size_t)(m0 + row) * N + n0 + chunk * 8] = v;
        }
    }
}

// ============================================================
// RPB MLP precompute -> fp16 table
// ============================================================
__global__ void rpb_kernel(
    const float* __restrict__ coords0, const float* __restrict__ coords1,
    const float* __restrict__ w1a, const float* __restrict__ b1a,
    const float* __restrict__ w2a, const float* __restrict__ b2a,
    const float* __restrict__ w1b, const float* __restrict__ b1b,
    const float* __restrict__ w2b, const float* __restrict__ b2b,
    __half* __restrict__ rpb)
{
    int t = blockIdx.x * blockDim.x + threadIdx.x;
    const int TOT = NQ_ * WA_ * KV_;
    if (t >= TOT) return;
    int j = t & 127;
    int i = (t >> 7) % WA_;
    int w = t / (KV_ * WA_);

    const float *co, *w1, *b1, *w2, *b2;
    int jj;
    if (j < TOPK_) { co = coords0; jj = j;          w1 = w1a; b1 = b1a; w2 = w2a; b2 = b2a; }
    else           { co = coords1; jj = j - TOPK_;  w1 = w1b; b1 = b1b; w2 = w2b; b2 = b2b; }

    size_t cbase = ((size_t)(w * WA_ + i) * TOPK_ + jj) * 2;
    float cy = co[cbase + 0];
    float cx = co[cbase + 1];

    float o0 = b2[0], o1 = b2[1], o2 = b2[2], o3 = b2[3];
#pragma unroll
    for (int tt = 0; tt < HD_; tt++) {
        float hsum = fmaxf(fmaf(w1[tt * 2], cy, fmaf(w1[tt * 2 + 1], cx, b1[tt])), 0.f);
        o0 = fmaf(w2[0 * HD_ + tt], hsum, o0);
        o1 = fmaf(w2[1 * HD_ + tt], hsum, o1);
        o2 = fmaf(w2[2 * HD_ + tt], hsum, o2);
        o3 = fmaf(w2[3 * HD_ + tt], hsum, o3);
    }
    size_t base = ((size_t)(w * H_) * WA_ + i) * KV_ + j;
    const size_t hstride = (size_t)WA_ * KV_;
    rpb[base + 0 * hstride] = __float2half(o0);
    rpb[base + 1 * hstride] = __float2half(o1);
    rpb[base + 2 * hstride] = __float2half(o2);
    rpb[base + 3 * hstride] = __float2half(o3);
}

// ============================================================
// FP16 attention, smem 36896 B:
//   k_s/v_s/out_s @0      [128][40]h (10240)
//   p region      @10240  rows 0..48 @528B + zero row 49 (26400)
//     q_s alias [64][40]h; p_s fp32 stride 132; p_h fp16 in-place
//   inv           @36640  f32[64] (256)
// ============================================================
#define SMEM_ATTN 36896

__global__ __launch_bounds__(256, 5) void attn_mma(
    const int* __restrict__ idx0, const int* __restrict__ idx1,
    const __half* __restrict__ rpb,
    const __half* __restrict__ qkv0, const __half* __restrict__ qkv1,
    __half* __restrict__ attn_out)
{
    extern __shared__ char smem_raw[];
    __half* k_s   = (__half*)(smem_raw);
    __half* v_s   = (__half*)(smem_raw);
    __half* out_s = (__half*)(smem_raw);
    float*  p_s   = (float*) (smem_raw + 10240);
    __half* q_s   = (__half*)(smem_raw + 10240);
    float*  inv_s = (float*) (smem_raw + 36640);
    char*   p_base = smem_raw + 10240;

    const int w = blockIdx.x, b = blockIdx.y, h = blockIdx.z;
    const int tid = threadIdx.x;
    const int warp = tid >> 5, lane = tid & 31;
    const int r = lane >> 2, cI = lane & 3;

    const int a_row  = lane & 15;
    const int a_koff = (lane >> 4) * 8;
    const int b_row  = (lane & 7) + (lane >> 4) * 8;
    const int b_koff = ((lane >> 3) & 1) * 8;

    // ---- gather K: 2 threads per key row ----
    const int j = tid >> 1;
    const int half16 = (tid & 1) * 16;
    const __half* basep;
    if (j < TOPK_) basep = qkv0 + ((size_t)b * P_ + idx0[w * TOPK_ + j]) * 384;
    else           basep = qkv1 + ((size_t)b * NQ_ + idx1[w * TOPK_ + (j - TOPK_)]) * 384;

    {
        const uint4* kp = (const uint4*)(basep + C_ + h * HD_ + half16);
        uint4 k0 = kp[0], k1 = kp[1];
        *(uint4*)&k_s[j * 40 + half16]     = k0;
        *(uint4*)&k_s[j * 40 + half16 + 8] = k1;
    }

    // ---- load Q (49 rows, pad to 64) ----
    const int wy = w >> 3, wx = w & 7;
    {
        int i = tid >> 2, d = (tid & 3) * 8;
        uint4 val = {0u, 0u, 0u, 0u};
        if (i < WA_) {
            int pos = (wy * WS_ + i / WS_) * RES_ + wx * WS_ + i % WS_;
            val = *(const uint4*)(qkv0 + ((size_t)b * P_ + pos) * 384 + h * HD_ + d);
        }
        *(uint4*)&q_s[i * 40 + d] = val;
    }
    __syncthreads();

    // ---- QK: M=64 N=128 K=32 ----
    float cq[2][4][4];
    {
        const int wm = (warp & 1) * 32, wn = (warp >> 1) * 32;
#pragma unroll
        for (int mt = 0; mt < 2; mt++)
#pragma unroll
            for (int nt = 0; nt < 4; nt++)
#pragma unroll
                for (int f = 0; f < 4; f++) cq[mt][nt][f] = 0.f;

#pragma unroll
        for (int k16 = 0; k16 < 32; k16 += 16) {
            uint32_t a[2][4], bb[4][2];
#pragma unroll
            for (int mt = 0; mt < 2; mt++) {
                uint32_t ad = sh_addr(&q_s[(wm + mt * 16 + a_row) * 40 + k16 + a_koff]);
                LDSM_X4(a[mt][0], a[mt][1], a[mt][2], a[mt][3], ad);
            }
#pragma unroll
            for (int np = 0; np < 2; np++) {
                uint32_t ad = sh_addr(&k_s[(wn + np * 16 + b_row) * 40 + k16 + b_koff]);
                LDSM_X4(bb[2 * np][0], bb[2 * np][1], bb[2 * np + 1][0], bb[2 * np + 1][1], ad);
            }
#pragma unroll
            for (int mt = 0; mt < 2; mt++)
#pragma unroll
                for (int nt = 0; nt < 4; nt++)
                    MMA_F16(cq[mt][nt][0], cq[mt][nt][1], cq[mt][nt][2], cq[mt][nt][3],
                            a[mt][0], a[mt][1], a[mt][2], a[mt][3],
                            bb[nt][0], bb[nt][1]);
        }
    }

    // ---- issue V gather loads ----
    uint4 vu0, vu1;
    {
        const uint4* vp = (const uint4*)(basep + 2 * C_ + h * HD_ + half16);
        vu0 = vp[0]; vu1 = vp[1];
    }
    __syncthreads();   // k_s, q_s dead

    // ---- epilogue: raw logits -> p_s; V rows -> v_s; zero the zero-row ----
    {
        const int wm = (warp & 1) * 32, wn = (warp >> 1) * 32;
#pragma unroll
        for (int mt = 0; mt < 2; mt++) {
            const int row0 = wm + mt * 16 + r;
            const int row1 = row0 + 8;
#pragma unroll
            for (int nt = 0; nt < 4; nt++) {
                const int col = wn + nt * 8 + cI * 2;
                if (row0 < WA_) {
                    float2 o = {cq[mt][nt][0], cq[mt][nt][1]};
                    *(float2*)&p_s[row0 * 132 + col] = o;
                }
                if (row1 < WA_) {
                    float2 o = {cq[mt][nt][2], cq[mt][nt][3]};
                    *(float2*)&p_s[row1 * 132 + col] = o;
                }
            }
        }
        if (tid < 132) *(uint32_t*)(p_base + WA_ * 528 + tid * 4) = 0u;

        *(uint4*)&v_s[j * 40 + half16]     = vu0;
        *(uint4*)&v_s[j * 40 + half16 + 8] = vu1;
    }
    __syncthreads();

    // ---- softmax: lane owns cols 2l,2l+1,64+2l,64+2l+1 (vectorized) ----
    const float scale = 0.17677669529663687f;
    const __half* rpb_wh = rpb + (size_t)(w * H_ + h) * WA_ * KV_;
    for (int i = warp; i < WA_; i += 8) {
        const __half* rrow = rpb_wh + i * KV_;
        float2 ra = __half22float2(*(const __half2*)&rrow[2 * lane]);
        float2 rb = __half22float2(*(const __half2*)&rrow[64 + 2 * lane]);
        float2 L0 = *(const float2*)&p_s[i * 132 + 2 * lane];
        float2 L1 = *(const float2*)&p_s[i * 132 + 64 + 2 * lane];
        float x0 = fmaf(L0.x, scale, ra.x);
        float x1 = fmaf(L0.y, scale, ra.y);
        float x2 = fmaf(L1.x, scale, rb.x);
        float x3 = fmaf(L1.y, scale, rb.y);
        float m = fmaxf(fmaxf(x0, x1), fmaxf(x2, x3));
#pragma unroll
        for (int off = 16; off; off >>= 1) m = fmaxf(m, __shfl_xor_sync(0xffffffffu, m, off));
        float e0 = __expf(x0 - m), e1 = __expf(x1 - m);
        float e2 = __expf(x2 - m), e3 = __expf(x3 - m);
        float s = e0 + e1 + e2 + e3;
#pragma unroll
        for (int off = 16; off; off >>= 1) s += __shfl_xor_sync(0xffffffffu, s, off);
        __half* ph = (__half*)(p_base + i * 528);
        *(uint32_t*)&ph[2 * lane]      = h2bits(e0, e1);
        *(uint32_t*)&ph[64 + 2 * lane] = h2bits(e2, e3);
        if (lane == 0) inv_s[i] = 1.f / s;
    }
    __syncthreads();

    // ---- PV: M=64 N=32 K=128; A rows >= WA_ remap to zero row ----
    {
        const int wm = (warp >> 1) * 16, wn = (warp & 1) * 16;
        const int vg = lane >> 3, vi = lane & 7;
        int row_a = wm + a_row;
        if (row_a >= WA_) row_a = WA_;   // zero row
        const char* pa = p_base + row_a * 528;
        float c[2][4];
#pragma unroll
        for (int nt = 0; nt < 2; nt++)
#pragma unroll
            for (int f = 0; f < 4; f++) c[nt][f] = 0.f;

#pragma unroll
        for (int k16 = 0; k16 < KV_; k16 += 16) {
            uint32_t a0, a1, a2, a3;
            {
                uint32_t ad = sh_addr(pa + (k16 + a_koff) * 2);
                LDSM_X4(a0, a1, a2, a3, ad);
            }
            uint32_t bfr[2][2];
            {
                uint32_t ad = sh_addr(&v_s[(k16 + (vg & 1) * 8 + vi) * 40 + wn + (vg >> 1) * 8]);
                LDSM_X4_T(bfr[0][0], bfr[0][1], bfr[1][0], bfr[1][1], ad);
            }
#pragma unroll
            for (int nt = 0; nt < 2; nt++)
                MMA_F16(c[nt][0], c[nt][1], c[nt][2], c[nt][3],
                        a0, a1, a2, a3, bfr[nt][0], bfr[nt][1]);
        }

        __syncthreads();   // v_s reads done; reuse region as out_s

        const int row0 = wm + r, row1 = wm + r + 8;
#pragma unroll
        for (int nt = 0; nt < 2; nt++) {
            const int col = wn + nt * 8 + cI * 2;
            if (row0 < WA_) {
                float inv = inv_s[row0];
                *(uint32_t*)&out_s[row0 * 40 + col] = h2bits(c[nt][0] * inv, c[nt][1] * inv);
            }
            if (row1 < WA_) {
                float inv = inv_s[row1];
                *(uint32_t*)&out_s[row1 * 40 + col] = h2bits(c[nt][2] * inv, c[nt][3] * inv);
            }
        }
    }
    __syncthreads();

    // ---- coalesced output: 49 rows x 32 halves (4 x uint4 per row) ----
    if (tid < WA_ * 4) {
        const int row = tid >> 2, chunk = tid & 3;
        uint4 v = *(const uint4*)&out_s[row * 40 + chunk * 8];
        *(uint4*)&attn_out[(((size_t)(b * NQ_ + w) * WA_) + row) * C_ + h * HD_ + chunk * 8] = v;
    }
}

// ============================================================
// launch
// ============================================================
extern "C" void kernel_launch(void* const* d_in, const int* in_sizes, int n_in,
                              void* d_out, int out_size)
{
    const float* x0      = (const float*)d_in[0];
    const float* x1      = (const float*)d_in[1];
    const float* qkv_w   = (const float*)d_in[2];
    const float* qkv_b   = (const float*)d_in[3];
    const float* proj_w  = (const float*)d_in[4];
    const float* proj_b  = (const float*)d_in[5];
    const float* rpb0_w1 = (const float*)d_in[6];
    const float* rpb0_b1 = (const float*)d_in[7];
    const float* rpb0_w2 = (const float*)d_in[8];
    const float* rpb0_b2 = (const float*)d_in[9];
    const float* rpb1_w1 = (const float*)d_in[10];
    const float* rpb1_b1 = (const float*)d_in[11];
    const float* rpb1_w2 = (const float*)d_in[12];
    const float* rpb1_b2 = (const float*)d_in[13];
    const float* coords0 = (const float*)d_in[14];
    const float* coords1 = (const float*)d_in[15];
    const int*   idx0    = (const int*)d_in[16];
    const int*   idx1    = (const int*)d_in[17];
    float* out = (float*)d_out;

    __half *qkv0, *qkv1, *rpb, *attn_out, *x0h, *x1h, *wqkv, *wproj;
    cudaGetSymbolAddress((void**)&qkv0, g_qkv0);
    cudaGetSymbolAddress((void**)&qkv1, g_qkv1);
    cudaGetSymbolAddress((void**)&rpb, g_rpb);
    cudaGetSymbolAddress((void**)&attn_out, g_attn_out);
    cudaGetSymbolAddress((void**)&x0h, g_x0h);
    cudaGetSymbolAddress((void**)&x1h, g_x1h);
    cudaGetSymbolAddress((void**)&wqkv, g_wqkv);
    cudaGetSymbolAddress((void**)&wproj, g_wproj);

    cudaFuncSetAttribute(attn_mma, cudaFuncAttributeMaxDynamicSharedMemorySize, SMEM_ATTN);

    cvt_f2h<<<592, 256>>>(x0, x0h, (int)((size_t)M0_ * C_ / 4));
    cvt_f2h<<<64, 256>>>(x1, x1h, M1_ * C_ / 4);
    cvt_f2h<<<48, 256>>>(qkv_w, wqkv, 384 * 128 / 4);
    cvt_f2h<<<16, 256>>>(proj_w, wproj, 128 * 128 / 4);

    gemm_h16<__half><<<dim3(M0_ / 128, 384 / 128), 256>>>(x0h, wqkv, qkv_b, qkv0, M0_, 384, 128);
    gemm_h16<__half><<<dim3(M1_ / 128, 384 / 128), 256>>>(x1h, wqkv, qkv_b, qkv1, M1_, 384, 128);
    rpb_kernel<<<(NQ_ * WA_ * KV_ + 255) / 256, 256>>>(
        coords0, coords1,
        rpb0_w1, rpb0_b1, rpb0_w2, rpb0_b2,
        rpb1_w1, rpb1_b1, rpb1_w2, rpb1_b2, rpb);
    attn_mma<<<dim3(NQ_, B_, H_), 256, SMEM_ATTN>>>(idx0, idx1, rpb, qkv0, qkv1, attn_out);
    gemm_h16<float><<<dim3(M0_ / 128, C_ / 128), 256>>>(attn_out, wproj, proj_b, out, M0_, C_, 128);
}